// round 6
// baseline (speedup 1.0000x reference)
#include <cuda_runtime.h>
#include <mma.h>
#include <cstdint>
#include <math.h>

using namespace nvcuda;

namespace {
constexpr int Bc = 16;
constexpr int Nc = 200;
constexpr int Dc = 2048;
constexpr int Hc = 2048;
constexpr int MTOK = Bc * Nc;       // 3200
constexpr int XR_ROWS = 3328;       // 26*128 padded
// proj pipeline: K chunks of 32 floats (128B rows)
constexpr int KC = Dc / 32;         // 64
constexpr int P_A_SZ = 128 * 128;   // 16 KB (A: 128 rows x 128B)
constexpr int P_B_SZ = 256 * 128;   // 32 KB (B: 256 rows x 128B)
constexpr int P_STAGE = P_A_SZ + P_B_SZ;   // 48 KB
constexpr int P_DYN = 3 * P_STAGE;  // 144 KB
// scores pipeline
constexpr int SKC = 32;             // chunks per K-slice (1024 floats)
constexpr int S_A_SZ = 64 * 128;    // 8 KB
constexpr int S_STAGE = 2 * S_A_SZ; // 16 KB
constexpr int S_DYN = 3 * S_STAGE;  // 48 KB
}

__device__ __align__(16) float g_xr[4][(size_t)XR_ROWS * Dc];
__device__ __align__(16) float g_wt[5][(size_t)Dc * Hc];
__device__ __align__(16) float g_lq  [(size_t)MTOK * Hc];
__device__ __align__(16) float g_lk  [(size_t)MTOK * Hc];
__device__ __align__(16) float g_lv  [(size_t)MTOK * Hc];
__device__ __align__(16) float g_lloc[(size_t)MTOK * Hc];
__device__ __align__(16) float g_kloc[(size_t)MTOK * Hc];
__device__ __align__(16) float g_a1  [(size_t)MTOK * Hc];
__device__ __align__(16) float g_a2  [(size_t)MTOK * Hc];
__device__ __align__(16) float g_spart[4][(size_t)MTOK * 256];
__device__ __align__(16) float g_scores[(size_t)Bc * Nc * Nc];

struct XPtrs { const float* x[4]; };
struct WPtrs { const float* w[5]; };
struct ProjArgs { const float* bias[5]; };

__device__ __forceinline__ uint32_t smem_u32(const void* p) {
    uint32_t a;
    asm("{ .reg .u64 t; cvta.to.shared.u64 t, %1; cvt.u32.u64 %0, t; }" : "=r"(a) : "l"(p));
    return a;
}
__device__ __forceinline__ float rna_tf32(float x) {
    float y; asm("cvt.rna.tf32.f32 %0, %1;" : "=f"(y) : "f"(x)); return y;
}
__device__ __forceinline__ void cp16_s(uint32_t d, const void* s) {
    asm volatile("cp.async.cg.shared.global [%0], [%1], 16;\n" :: "r"(d), "l"(s));
}
__device__ __forceinline__ void cp_commit() { asm volatile("cp.async.commit_group;\n"); }
template <int N> __device__ __forceinline__ void cp_wait() {
    asm volatile("cp.async.wait_group %0;\n" :: "n"(N));
}
#define LDSM4(d, addr) \
    asm volatile("ldmatrix.sync.aligned.m8n8.x4.shared.b16 {%0,%1,%2,%3}, [%4];" \
        : "=r"((d)[0]), "=r"((d)[1]), "=r"((d)[2]), "=r"((d)[3]) : "r"(addr))
#define MMA_TF32(c, a, b0v, b1v) \
    asm volatile("mma.sync.aligned.m16n8k8.row.col.f32.tf32.tf32.f32 " \
        "{%0,%1,%2,%3}, {%4,%5,%6,%7}, {%8,%9}, {%0,%1,%2,%3};" \
        : "+f"((c)[0]), "+f"((c)[1]), "+f"((c)[2]), "+f"((c)[3]) \
        : "r"((a)[0]), "r"((a)[1]), "r"((a)[2]), "r"((a)[3]), "r"(b0v), "r"(b1v))

// ---- prep: tf32-round X into padded scratch -------------------------------
__global__ __launch_bounds__(256) void round_x_kernel(XPtrs xp) {
    const int j = blockIdx.z;
    const float4* src = reinterpret_cast<const float4*>(xp.x[j]);
    float4* dst = reinterpret_cast<float4*>(g_xr[j]);
    const int idx = blockIdx.x * 256 + threadIdx.x;
    float4 v = src[idx];
    v.x = rna_tf32(v.x); v.y = rna_tf32(v.y); v.z = rna_tf32(v.z); v.w = rna_tf32(v.w);
    dst[idx] = v;
}

// ---- prep: W[k][n] -> Wt[n][k], tf32-rounded ------------------------------
__global__ __launch_bounds__(256) void transW_kernel(WPtrs wp) {
    __shared__ float t[32][33];
    const int j = blockIdx.z;
    const float* W = wp.w[j];
    float* Wt = g_wt[j];
    const int tx = threadIdx.x, ty = threadIdx.y;
    const int n0 = blockIdx.x * 32, k0 = blockIdx.y * 32;
    #pragma unroll
    for (int i = 0; i < 4; i++)
        t[ty + 8 * i][tx] = rna_tf32(W[(size_t)(k0 + ty + 8 * i) * Hc + n0 + tx]);
    __syncthreads();
    #pragma unroll
    for (int i = 0; i < 4; i++)
        Wt[(size_t)(n0 + ty + 8 * i) * Dc + k0 + tx] = t[tx][ty + 8 * i];
}

// ---- prep for scores ------------------------------------------------------
__global__ __launch_bounds__(256) void add_round_kernel(const float* __restrict__ param) {
    const int idx = blockIdx.x * 256 + threadIdx.x;   // float4 index
    const float4 lq = reinterpret_cast<const float4*>(g_lq)[idx];
    const float4 pv = reinterpret_cast<const float4*>(param)[idx];
    const float4 ll = reinterpret_cast<const float4*>(g_lloc)[idx];
    float4 a1, a2;
    a1.x = rna_tf32(lq.x + pv.x); a1.y = rna_tf32(lq.y + pv.y);
    a1.z = rna_tf32(lq.z + pv.z); a1.w = rna_tf32(lq.w + pv.w);
    a2.x = rna_tf32(lq.x + ll.x); a2.y = rna_tf32(lq.y + ll.y);
    a2.z = rna_tf32(lq.z + ll.z); a2.w = rna_tf32(lq.w + ll.w);
    reinterpret_cast<float4*>(g_a1)[idx] = a1;
    reinterpret_cast<float4*>(g_a2)[idx] = a2;
    float4 k1 = reinterpret_cast<const float4*>(g_lk)[idx];
    k1.x = rna_tf32(k1.x); k1.y = rna_tf32(k1.y); k1.z = rna_tf32(k1.z); k1.w = rna_tf32(k1.w);
    reinterpret_cast<float4*>(g_lk)[idx] = k1;
    float4 k2 = reinterpret_cast<const float4*>(g_kloc)[idx];
    k2.x = rna_tf32(k2.x); k2.y = rna_tf32(k2.y); k2.z = rna_tf32(k2.z); k2.w = rna_tf32(k2.w);
    reinterpret_cast<float4*>(g_kloc)[idx] = k2;
}

// ---- tf32 mma.sync projection GEMM: 128x256 CTA, 64x64 warp tiles ---------
// A = g_xr [m][k], B = g_wt [n][k] (both K-major). Y = A@B^T + bias.
__global__ __launch_bounds__(256, 1) void proj_mma(ProjArgs pa) {
    extern __shared__ char dynraw[];
    const int z = blockIdx.z;
    const float* Xr = g_xr[z <= 2 ? z : 3];
    const float* Wt = g_wt[z];
    const float* bias = pa.bias[z];
    float* Y;
    switch (z) {
        case 0:  Y = g_lq;   break;
        case 1:  Y = g_lk;   break;
        case 2:  Y = g_lv;   break;
        case 3:  Y = g_lloc; break;
        default: Y = g_kloc; break;
    }
    const int nBase = blockIdx.x * 256;
    const int mBase = blockIdx.y * 128;
    const int tid = threadIdx.x;
    const int wid = tid >> 5;
    const int lane = tid & 31;
    const int warpM = (wid & 1) * 64;    // 0 or 64
    const int warpN = (wid >> 1) * 64;   // 0,64,128,192
    const uint32_t smemBase = smem_u32(dynraw);

    const int rL = (lane & 7) + 8 * ((lane >> 3) & 1);   // 0-15
    const int cIdx = lane >> 4;                          // 0/1 (16B half)
    const int xr = rL & 7;

    auto load_stage = [&](int s, int kc) {
        const uint32_t base = smemBase + s * P_STAGE;
        const float* xs = Xr + (size_t)mBase * Dc + kc * 32;
        const float* ws = Wt + (size_t)nBase * Dc + kc * 32;
        #pragma unroll
        for (int i = 0; i < 4; i++) {
            int idx = tid + i * 256;
            int r = idx >> 3, j = idx & 7;
            cp16_s(base + r * 128 + ((j ^ (r & 7)) << 4), xs + (size_t)r * Dc + j * 4);
        }
        #pragma unroll
        for (int i = 0; i < 8; i++) {
            int idx = tid + i * 256;
            int r = idx >> 3, j = idx & 7;
            cp16_s(base + P_A_SZ + r * 128 + ((j ^ (r & 7)) << 4), ws + (size_t)r * Dc + j * 4);
        }
    };

    float acc[4][8][4];
    #pragma unroll
    for (int mt = 0; mt < 4; mt++)
        #pragma unroll
        for (int nt = 0; nt < 8; nt++)
            #pragma unroll
            for (int q = 0; q < 4; q++) acc[mt][nt][q] = 0.0f;

    load_stage(0, 0); cp_commit();
    load_stage(1, 1); cp_commit();

    for (int kc = 0; kc < KC; kc++) {
        const int s = kc % 3;
        cp_wait<1>();
        __syncthreads();
        if (kc + 2 < KC) load_stage((kc + 2) % 3, kc + 2);
        cp_commit();

        const uint32_t aBase = smemBase + s * P_STAGE;
        const uint32_t bBase = aBase + P_A_SZ;
        #pragma unroll
        for (int ks = 0; ks < 4; ks++) {
            const int ch = ((2 * ks + cIdx) ^ xr) << 4;
            uint32_t aF[4][4], bF[4][4];
            #pragma unroll
            for (int mt = 0; mt < 4; mt++)
                LDSM4(aF[mt], aBase + (warpM + mt * 16 + rL) * 128 + ch);
            #pragma unroll
            for (int p = 0; p < 4; p++)
                LDSM4(bF[p], bBase + (warpN + p * 16 + rL) * 128 + ch);
            #pragma unroll
            for (int mt = 0; mt < 4; mt++)
                #pragma unroll
                for (int nt = 0; nt < 8; nt++) {
                    const int p = nt >> 1, sel = nt & 1;
                    MMA_TF32(acc[mt][nt], aF[mt], bF[p][sel], bF[p][sel + 2]);
                }
        }
    }

    const int lr = lane >> 2;
    const int lc = (lane & 3) * 2;
    #pragma unroll
    for (int mt = 0; mt < 4; mt++) {
        const int r0 = mBase + warpM + mt * 16 + lr;
        #pragma unroll
        for (int nt = 0; nt < 8; nt++) {
            const int col = nBase + warpN + nt * 8 + lc;
            const float2 bv = *reinterpret_cast<const float2*>(&bias[col]);
            if (r0 < MTOK) {
                float2 v = make_float2(acc[mt][nt][0] + bv.x, acc[mt][nt][1] + bv.y);
                *reinterpret_cast<float2*>(&Y[(size_t)r0 * Hc + col]) = v;
            }
            if (r0 + 8 < MTOK) {
                float2 v = make_float2(acc[mt][nt][2] + bv.x, acc[mt][nt][3] + bv.y);
                *reinterpret_cast<float2*>(&Y[(size_t)(r0 + 8) * Hc + col]) = v;
            }
        }
    }
}

// ---- scores: split-K mma.sync (unchanged) ---------------------------------
__global__ __launch_bounds__(128, 1) void scores_mma() {
    extern __shared__ char dynraw[];
    const int b = blockIdx.z >> 2;
    const int sl = blockIdx.z & 3;
    const float* Asrc = (sl < 2 ? g_a1 : g_a2) + (size_t)b * Nc * Dc + (sl & 1) * 1024;
    const float* Bsrc = (sl < 2 ? g_lk : g_kloc) + (size_t)b * Nc * Dc + (sl & 1) * 1024;
    const int nBase = blockIdx.y * 64;
    const int mBase = blockIdx.x * 64;
    const int tid = threadIdx.x;
    const int wid = tid >> 5;
    const int lane = tid & 31;
    const int warpM = (wid >> 1) * 32;
    const int warpN = (wid & 1) * 32;
    const uint32_t smemBase = smem_u32(dynraw);

    const int rL = (lane & 7) + 8 * ((lane >> 3) & 1);
    const int cIdx = lane >> 4;
    const int xr = rL & 7;

    auto load_stage = [&](int s, int kc) {
        const uint32_t base = smemBase + s * S_STAGE;
        #pragma unroll
        for (int i = 0; i < 4; i++) {
            int idx = tid + i * 128;
            int r = idx >> 3, j = idx & 7;
            int row = nBase + r; if (row > Nc - 1) row = Nc - 1;
            cp16_s(base + r * 128 + ((j ^ (r & 7)) << 4),
                   Asrc + (size_t)row * Dc + kc * 32 + j * 4);
        }
        #pragma unroll
        for (int i = 0; i < 4; i++) {
            int idx = tid + i * 128;
            int r = idx >> 3, j = idx & 7;
            int row = mBase + r; if (row > Nc - 1) row = Nc - 1;
            cp16_s(base + S_A_SZ + r * 128 + ((j ^ (r & 7)) << 4),
                   Bsrc + (size_t)row * Dc + kc * 32 + j * 4);
        }
    };

    float acc[2][4][4];
    #pragma unroll
    for (int mt = 0; mt < 2; mt++)
        #pragma unroll
        for (int nt = 0; nt < 4; nt++)
            #pragma unroll
            for (int q = 0; q < 4; q++) acc[mt][nt][q] = 0.0f;

    load_stage(0, 0); cp_commit();
    load_stage(1, 1); cp_commit();

    for (int kc = 0; kc < SKC; kc++) {
        const int s = kc % 3;
        cp_wait<1>();
        __syncthreads();
        if (kc + 2 < SKC) load_stage((kc + 2) % 3, kc + 2);
        cp_commit();

        const uint32_t aBase = smemBase + s * S_STAGE;
        const uint32_t bBase = aBase + S_A_SZ;
        #pragma unroll
        for (int ks = 0; ks < 4; ks++) {
            const int ch = ((2 * ks + cIdx) ^ xr) << 4;
            uint32_t aF[2][4], bF[2][4];
            #pragma unroll
            for (int mt = 0; mt < 2; mt++)
                LDSM4(aF[mt], aBase + (warpM + mt * 16 + rL) * 128 + ch);
            #pragma unroll
            for (int p = 0; p < 2; p++)
                LDSM4(bF[p], bBase + (warpN + p * 16 + rL) * 128 + ch);
            #pragma unroll
            for (int mt = 0; mt < 2; mt++)
                #pragma unroll
                for (int nt = 0; nt < 4; nt++) {
                    const int p = nt >> 1, sel = nt & 1;
                    MMA_TF32(acc[mt][nt], aF[mt], bF[p][sel], bF[p][sel + 2]);
                }
        }
    }

    float* part = g_spart[sl];
    const int lr = lane >> 2;
    const int lc = (lane & 3) * 2;
    #pragma unroll
    for (int mt = 0; mt < 2; mt++) {
        const int n0 = nBase + warpM + mt * 16 + lr;
        #pragma unroll
        for (int nt = 0; nt < 4; nt++) {
            const int col = mBase + warpN + nt * 8 + lc;
            if (col < Nc) {
                if (n0 < Nc) {
                    float2 v = make_float2(acc[mt][nt][0], acc[mt][nt][1]);
                    *reinterpret_cast<float2*>(&part[((size_t)(b * Nc + n0)) * 256 + col]) = v;
                }
                if (n0 + 8 < Nc) {
                    float2 v = make_float2(acc[mt][nt][2], acc[mt][nt][3]);
                    *reinterpret_cast<float2*>(&part[((size_t)(b * Nc + n0 + 8)) * 256 + col]) = v;
                }
            }
        }
    }
}

// ---- softmax: sum 4 partials, scale, softmax ------------------------------
__global__ __launch_bounds__(256) void softmax_kernel() {
    const int row = blockIdx.x;
    const int t = threadIdx.x;
    const float SC = 0.022097086912079608f;  // 1/sqrt(2048)
    __shared__ float red[256];
    float v = -1e30f;
    if (t < Nc) {
        float s = g_spart[0][(size_t)row * 256 + t] + g_spart[1][(size_t)row * 256 + t]
                + g_spart[2][(size_t)row * 256 + t] + g_spart[3][(size_t)row * 256 + t];
        v = s * SC;
    }
    red[t] = v;
    __syncthreads();
    #pragma unroll
    for (int s = 128; s > 0; s >>= 1) {
        if (t < s) red[t] = fmaxf(red[t], red[t + s]);
        __syncthreads();
    }
    float mx = red[0];
    __syncthreads();
    float e = (t < Nc) ? expf(v - mx) : 0.0f;
    red[t] = e;
    __syncthreads();
    #pragma unroll
    for (int s = 128; s > 0; s >>= 1) {
        if (t < s) red[t] += red[t + s];
        __syncthreads();
    }
    float inv = 1.0f / red[0];
    if (t < Nc) g_scores[(size_t)row * Nc + t] = e * inv;
}

// ---- out = attn @ lv (wmma) ----------------------------------------------
__global__ __launch_bounds__(128) void out_kernel(float* __restrict__ out) {
    const int b = blockIdx.z;
    const int nBase = blockIdx.y * 64;
    const int hBase = blockIdx.x * 64;
    const int tid = threadIdx.x;
    const int wid = tid >> 5;
    const int warpM = (wid >> 1) * 32;
    const int warpN = (wid & 1) * 32;
    __shared__ union {
        struct { float As[64][20]; float Bs[16][68]; } ld;
        float out[64][64];
    } sm;
    wmma::fragment<wmma::accumulator, 16, 16, 8, float> cfr[2][2];
    #pragma unroll
    for (int i = 0; i < 2; i++)
        #pragma unroll
        for (int j = 0; j < 2; j++) wmma::fill_fragment(cfr[i][j], 0.0f);
    const float* attn = g_scores + (size_t)b * Nc * Nc;
    const float* lvb  = g_lv + (size_t)b * Nc * Hc;
    const int kTiles = (Nc + 15) / 16;
    for (int kt = 0; kt < kTiles; kt++) {
        #pragma unroll
        for (int i = 0; i < 2; i++) {
            int idx = tid + i * 128;
            int r = idx >> 2, c4 = (idx & 3) * 4;
            int n = nBase + r, k = kt * 16 + c4;
            float4 v = make_float4(0.f, 0.f, 0.f, 0.f);
            if (n < Nc && k < Nc) v = *reinterpret_cast<const float4*>(&attn[(size_t)n * Nc + k]);
            *reinterpret_cast<float4*>(&sm.ld.As[r][c4]) = v;
        }
        #pragma unroll
        for (int i = 0; i < 2; i++) {
            int idx = tid + i * 128;
            int r = idx >> 4, c4 = (idx & 15) * 4;
            int k = kt * 16 + r;
            float4 v = make_float4(0.f, 0.f, 0.f, 0.f);
            if (k < Nc) v = *reinterpret_cast<const float4*>(&lvb[(size_t)k * Hc + hBase + c4]);
            *reinterpret_cast<float4*>(&sm.ld.Bs[r][c4]) = v;
        }
        __syncthreads();
        #pragma unroll
        for (int ks = 0; ks < 2; ks++) {
            wmma::fragment<wmma::matrix_a, 16, 16, 8, wmma::precision::tf32, wmma::row_major> af[2];
            wmma::fragment<wmma::matrix_b, 16, 16, 8, wmma::precision::tf32, wmma::row_major> bf[2];
            #pragma unroll
            for (int i = 0; i < 2; i++) {
                wmma::load_matrix_sync(af[i], &sm.ld.As[warpM + i * 16][ks * 8], 20);
                #pragma unroll
                for (int t = 0; t < af[i].num_elements; t++) af[i].x[t] = wmma::__float_to_tf32(af[i].x[t]);
            }
            #pragma unroll
            for (int j = 0; j < 2; j++) {
                wmma::load_matrix_sync(bf[j], &sm.ld.Bs[ks * 8][warpN + j * 16], 68);
                #pragma unroll
                for (int t = 0; t < bf[j].num_elements; t++) bf[j].x[t] = wmma::__float_to_tf32(bf[j].x[t]);
            }
            #pragma unroll
            for (int i = 0; i < 2; i++)
                #pragma unroll
                for (int j = 0; j < 2; j++) wmma::mma_sync(cfr[i][j], af[i], bf[j], cfr[i][j]);
        }
        __syncthreads();
    }
    #pragma unroll
    for (int i = 0; i < 2; i++)
        #pragma unroll
        for (int j = 0; j < 2; j++)
            wmma::store_matrix_sync(&sm.out[warpM + i * 16][warpN + j * 16], cfr[i][j], 64, wmma::mem_row_major);
    __syncthreads();
    #pragma unroll
    for (int it = 0; it < 8; it++) {
        int fid = tid + it * 128;
        int r = fid >> 4, c4 = (fid & 15) * 4;
        int n = nBase + r;
        if (n < Nc)
            *reinterpret_cast<float4*>(&out[((size_t)b * Nc + n) * Hc + hBase + c4]) =
                *reinterpret_cast<float4*>(&sm.out[r][c4]);
    }
}

// ---------------------------------------------------------------------------
extern "C" void kernel_launch(void* const* d_in, const int* in_sizes, int n_in,
                              void* d_out, int out_size) {
    (void)in_sizes; (void)n_in; (void)out_size;
    XPtrs xp;
    xp.x[0] = (const float*)d_in[0];
    xp.x[1] = (const float*)d_in[1];
    xp.x[2] = (const float*)d_in[2];
    xp.x[3] = (const float*)d_in[3];
    WPtrs wp;
    wp.w[0] = (const float*)d_in[4];
    wp.w[1] = (const float*)d_in[6];
    wp.w[2] = (const float*)d_in[8];
    wp.w[3] = (const float*)d_in[10];
    wp.w[4] = (const float*)d_in[12];
    ProjArgs pa;
    pa.bias[0] = (const float*)d_in[5];
    pa.bias[1] = (const float*)d_in[7];
    pa.bias[2] = (const float*)d_in[9];
    pa.bias[3] = (const float*)d_in[11];
    pa.bias[4] = (const float*)d_in[13];
    const float* param = (const float*)d_in[14];

    cudaFuncSetAttribute(proj_mma, cudaFuncAttributeMaxDynamicSharedMemorySize, P_DYN);
    cudaFuncSetAttribute(scores_mma, cudaFuncAttributeMaxDynamicSharedMemorySize, S_DYN);

    round_x_kernel<<<dim3(MTOK * Dc / 4 / 256, 1, 4), 256>>>(xp);
    transW_kernel<<<dim3(Hc / 32, Dc / 32, 5), dim3(32, 8)>>>(wp);
    proj_mma<<<dim3(Hc / 256, XR_ROWS / 128, 5), 256, P_DYN>>>(pa);
    add_round_kernel<<<MTOK * Dc / 4 / 256, 256>>>(param);
    scores_mma<<<dim3(4, 4, Bc * 4), 128, S_DYN>>>();
    softmax_kernel<<<MTOK, 256>>>();
    out_kernel<<<dim3(Hc / 64, (Nc + 63) / 64, Bc), 128>>>((float*)d_out);
}

// round 8
// speedup vs baseline: 1.0751x; 1.0751x over previous
#include <cuda_runtime.h>
#include <mma.h>
#include <cstdint>
#include <math.h>

using namespace nvcuda;

namespace {
constexpr int Bc = 16;
constexpr int Nc = 200;
constexpr int Dc = 2048;
constexpr int Hc = 2048;
constexpr int MTOK = Bc * Nc;       // 3200
constexpr int XR_ROWS = 3328;       // 26*128 padded
constexpr int KC = Dc / 32;         // 64
constexpr int P_A_SZ = 128 * 128;   // 16 KB
constexpr int P_STAGE = 2 * P_A_SZ; // 32 KB
constexpr int P_DYN = 3 * P_STAGE;  // 96 KB
constexpr int SKC = 32;
constexpr int S_A_SZ = 64 * 128;    // 8 KB
constexpr int S_STAGE = 2 * S_A_SZ; // 16 KB
constexpr int S_DYN = 3 * S_STAGE;  // 48 KB
}

__device__ __align__(16) float g_xr[4][(size_t)XR_ROWS * Dc];
__device__ __align__(16) float g_wt[5][(size_t)Dc * Hc];
__device__ __align__(16) float g_lq  [(size_t)MTOK * Hc];
__device__ __align__(16) float g_lk  [(size_t)MTOK * Hc];
__device__ __align__(16) float g_lv  [(size_t)MTOK * Hc];
__device__ __align__(16) float g_lloc[(size_t)MTOK * Hc];
__device__ __align__(16) float g_kloc[(size_t)MTOK * Hc];
__device__ __align__(16) float g_a1  [(size_t)MTOK * Hc];
__device__ __align__(16) float g_a2  [(size_t)MTOK * Hc];
__device__ __align__(16) float g_spart[4][(size_t)MTOK * 256];
__device__ __align__(16) float g_scores[(size_t)Bc * Nc * Nc];

struct XPtrs { const float* x[4]; };
struct WPtrs { const float* w[5]; };
struct ProjArgs { const float* bias[5]; };

__device__ __forceinline__ uint32_t smem_u32(const void* p) {
    uint32_t a;
    asm("{ .reg .u64 t; cvta.to.shared.u64 t, %1; cvt.u32.u64 %0, t; }" : "=r"(a) : "l"(p));
    return a;
}
__device__ __forceinline__ float rna_tf32(float x) {
    float y; asm("cvt.rna.tf32.f32 %0, %1;" : "=f"(y) : "f"(x)); return y;
}
__device__ __forceinline__ void cp16_s(uint32_t d, const void* s) {
    asm volatile("cp.async.cg.shared.global [%0], [%1], 16;\n" :: "r"(d), "l"(s));
}
__device__ __forceinline__ void cp_commit() { asm volatile("cp.async.commit_group;\n"); }
template <int N> __device__ __forceinline__ void cp_wait() {
    asm volatile("cp.async.wait_group %0;\n" :: "n"(N));
}
#define LDSM4(d, addr) \
    asm volatile("ldmatrix.sync.aligned.m8n8.x4.shared.b16 {%0,%1,%2,%3}, [%4];" \
        : "=r"((d)[0]), "=r"((d)[1]), "=r"((d)[2]), "=r"((d)[3]) : "r"(addr))
#define MMA_TF32(c, a, b0v, b1v) \
    asm volatile("mma.sync.aligned.m16n8k8.row.col.f32.tf32.tf32.f32 " \
        "{%0,%1,%2,%3}, {%4,%5,%6,%7}, {%8,%9}, {%0,%1,%2,%3};" \
        : "+f"((c)[0]), "+f"((c)[1]), "+f"((c)[2]), "+f"((c)[3]) \
        : "r"((a)[0]), "r"((a)[1]), "r"((a)[2]), "r"((a)[3]), "r"(b0v), "r"(b1v))

// ---- prep: tf32-round X into padded scratch -------------------------------
__global__ __launch_bounds__(256) void round_x_kernel(XPtrs xp) {
    const int j = blockIdx.z;
    const float4* src = reinterpret_cast<const float4*>(xp.x[j]);
    float4* dst = reinterpret_cast<float4*>(g_xr[j]);
    const int idx = blockIdx.x * 256 + threadIdx.x;
    float4 v = src[idx];
    v.x = rna_tf32(v.x); v.y = rna_tf32(v.y); v.z = rna_tf32(v.z); v.w = rna_tf32(v.w);
    dst[idx] = v;
}

// ---- prep: W[k][n] -> Wt[n][k], tf32-rounded ------------------------------
__global__ __launch_bounds__(256) void transW_kernel(WPtrs wp) {
    __shared__ float t[32][33];
    const int j = blockIdx.z;
    const float* W = wp.w[j];
    float* Wt = g_wt[j];
    const int tx = threadIdx.x, ty = threadIdx.y;
    const int n0 = blockIdx.x * 32, k0 = blockIdx.y * 32;
    #pragma unroll
    for (int i = 0; i < 4; i++)
        t[ty + 8 * i][tx] = rna_tf32(W[(size_t)(k0 + ty + 8 * i) * Hc + n0 + tx]);
    __syncthreads();
    #pragma unroll
    for (int i = 0; i < 4; i++)
        Wt[(size_t)(n0 + ty + 8 * i) * Dc + k0 + tx] = t[tx][ty + 8 * i];
}

// ---- prep for scores: a1 = rna(lq+param), a2 = rna(lq+lloc) ---------------
// (lk/kloc are now rounded in proj epilogue)
__global__ __launch_bounds__(256) void add_round_kernel(const float* __restrict__ param) {
    const int idx = blockIdx.x * 256 + threadIdx.x;   // float4 index
    const float4 lq = reinterpret_cast<const float4*>(g_lq)[idx];
    const float4 pv = reinterpret_cast<const float4*>(param)[idx];
    const float4 ll = reinterpret_cast<const float4*>(g_lloc)[idx];
    float4 a1, a2;
    a1.x = rna_tf32(lq.x + pv.x); a1.y = rna_tf32(lq.y + pv.y);
    a1.z = rna_tf32(lq.z + pv.z); a1.w = rna_tf32(lq.w + pv.w);
    a2.x = rna_tf32(lq.x + ll.x); a2.y = rna_tf32(lq.y + ll.y);
    a2.z = rna_tf32(lq.z + ll.z); a2.w = rna_tf32(lq.w + ll.w);
    reinterpret_cast<float4*>(g_a1)[idx] = a1;
    reinterpret_cast<float4*>(g_a2)[idx] = a2;
}

// ---- tf32 mma.sync projection GEMM: 128x128 CTA, 64x32 warps, 2 CTA/SM ----
__global__ __launch_bounds__(256, 2) void proj_mma(ProjArgs pa) {
    extern __shared__ char dynraw[];
    const int z = blockIdx.z;
    const float* Xr = g_xr[z <= 2 ? z : 3];
    const float* Wt = g_wt[z];
    const float* bias = pa.bias[z];
    float* Y;
    switch (z) {
        case 0:  Y = g_lq;   break;
        case 1:  Y = g_lk;   break;
        case 2:  Y = g_lv;   break;
        case 3:  Y = g_lloc; break;
        default: Y = g_kloc; break;
    }
    const bool doRound = (z == 1) || (z == 4);   // lk, kloc consumed as tf32
    const int nBase = blockIdx.x * 128;
    const int mBase = blockIdx.y * 128;
    const int tid = threadIdx.x;
    const int wid = tid >> 5;
    const int lane = tid & 31;
    const int warpM = (wid >> 2) * 64;   // 0 or 64
    const int warpN = (wid & 3) * 32;    // 0,32,64,96
    const uint32_t smemBase = smem_u32(dynraw);

    const int rL = (lane & 7) + 8 * ((lane >> 3) & 1);   // 0-15
    const int cIdx = lane >> 4;                          // 0/1
    const int xr = rL & 7;

    auto load_stage = [&](int s, int kc) {
        const uint32_t base = smemBase + s * P_STAGE;
        const float* xs = Xr + (size_t)mBase * Dc + kc * 32;
        const float* ws = Wt + (size_t)nBase * Dc + kc * 32;
        #pragma unroll
        for (int i = 0; i < 4; i++) {
            int idx = tid + i * 256;
            int r = idx >> 3, j = idx & 7;
            cp16_s(base + r * 128 + ((j ^ (r & 7)) << 4), xs + (size_t)r * Dc + j * 4);
        }
        #pragma unroll
        for (int i = 0; i < 4; i++) {
            int idx = tid + i * 256;
            int r = idx >> 3, j = idx & 7;
            cp16_s(base + P_A_SZ + r * 128 + ((j ^ (r & 7)) << 4), ws + (size_t)r * Dc + j * 4);
        }
    };

    float acc[4][4][4];
    #pragma unroll
    for (int mt = 0; mt < 4; mt++)
        #pragma unroll
        for (int nt = 0; nt < 4; nt++)
            #pragma unroll
            for (int q = 0; q < 4; q++) acc[mt][nt][q] = 0.0f;

    load_stage(0, 0); cp_commit();
    load_stage(1, 1); cp_commit();

    for (int kc = 0; kc < KC; kc++) {
        const int s = kc % 3;
        cp_wait<1>();
        __syncthreads();
        if (kc + 2 < KC) load_stage((kc + 2) % 3, kc + 2);
        cp_commit();

        const uint32_t aBase = smemBase + s * P_STAGE;
        const uint32_t bBase = aBase + P_A_SZ;
        #pragma unroll
        for (int ks = 0; ks < 4; ks++) {
            const int ch = ((2 * ks + cIdx) ^ xr) << 4;
            uint32_t aF[4][4], bF[2][4];
            #pragma unroll
            for (int mt = 0; mt < 4; mt++)
                LDSM4(aF[mt], aBase + (warpM + mt * 16 + rL) * 128 + ch);
            #pragma unroll
            for (int p = 0; p < 2; p++)
                LDSM4(bF[p], bBase + (warpN + p * 16 + rL) * 128 + ch);
            #pragma unroll
            for (int mt = 0; mt < 4; mt++)
                #pragma unroll
                for (int nt = 0; nt < 4; nt++) {
                    const int p = nt >> 1, sel = nt & 1;
                    MMA_TF32(acc[mt][nt], aF[mt], bF[p][sel], bF[p][sel + 2]);
                }
        }
    }

    const int lr = lane >> 2;
    const int lc = (lane & 3) * 2;
    #pragma unroll
    for (int mt = 0; mt < 4; mt++) {
        const int r0 = mBase + warpM + mt * 16 + lr;
        #pragma unroll
        for (int nt = 0; nt < 4; nt++) {
            const int col = nBase + warpN + nt * 8 + lc;
            const float2 bv = *reinterpret_cast<const float2*>(&bias[col]);
            float2 v0 = make_float2(acc[mt][nt][0] + bv.x, acc[mt][nt][1] + bv.y);
            float2 v1 = make_float2(acc[mt][nt][2] + bv.x, acc[mt][nt][3] + bv.y);
            if (doRound) {
                v0.x = rna_tf32(v0.x); v0.y = rna_tf32(v0.y);
                v1.x = rna_tf32(v1.x); v1.y = rna_tf32(v1.y);
            }
            if (r0 < MTOK)
                *reinterpret_cast<float2*>(&Y[(size_t)r0 * Hc + col]) = v0;
            if (r0 + 8 < MTOK)
                *reinterpret_cast<float2*>(&Y[(size_t)(r0 + 8) * Hc + col]) = v1;
        }
    }
}

// ---- scores: split-K mma.sync (unchanged) ---------------------------------
__global__ __launch_bounds__(128, 1) void scores_mma() {
    extern __shared__ char dynraw[];
    const int b = blockIdx.z >> 2;
    const int sl = blockIdx.z & 3;
    const float* Asrc = (sl < 2 ? g_a1 : g_a2) + (size_t)b * Nc * Dc + (sl & 1) * 1024;
    const float* Bsrc = (sl < 2 ? g_lk : g_kloc) + (size_t)b * Nc * Dc + (sl & 1) * 1024;
    const int nBase = blockIdx.y * 64;
    const int mBase = blockIdx.x * 64;
    const int tid = threadIdx.x;
    const int wid = tid >> 5;
    const int lane = tid & 31;
    const int warpM = (wid >> 1) * 32;
    const int warpN = (wid & 1) * 32;
    const uint32_t smemBase = smem_u32(dynraw);

    const int rL = (lane & 7) + 8 * ((lane >> 3) & 1);
    const int cIdx = lane >> 4;
    const int xr = rL & 7;

    auto load_stage = [&](int s, int kc) {
        const uint32_t base = smemBase + s * S_STAGE;
        #pragma unroll
        for (int i = 0; i < 4; i++) {
            int idx = tid + i * 128;
            int r = idx >> 3, j = idx & 7;
            int row = nBase + r; if (row > Nc - 1) row = Nc - 1;
            cp16_s(base + r * 128 + ((j ^ (r & 7)) << 4),
                   Asrc + (size_t)row * Dc + kc * 32 + j * 4);
        }
        #pragma unroll
        for (int i = 0; i < 4; i++) {
            int idx = tid + i * 128;
            int r = idx >> 3, j = idx & 7;
            int row = mBase + r; if (row > Nc - 1) row = Nc - 1;
            cp16_s(base + S_A_SZ + r * 128 + ((j ^ (r & 7)) << 4),
                   Bsrc + (size_t)row * Dc + kc * 32 + j * 4);
        }
    };

    float acc[2][4][4];
    #pragma unroll
    for (int mt = 0; mt < 2; mt++)
        #pragma unroll
        for (int nt = 0; nt < 4; nt++)
            #pragma unroll
            for (int q = 0; q < 4; q++) acc[mt][nt][q] = 0.0f;

    load_stage(0, 0); cp_commit();
    load_stage(1, 1); cp_commit();

    for (int kc = 0; kc < SKC; kc++) {
        const int s = kc % 3;
        cp_wait<1>();
        __syncthreads();
        if (kc + 2 < SKC) load_stage((kc + 2) % 3, kc + 2);
        cp_commit();

        const uint32_t aBase = smemBase + s * S_STAGE;
        const uint32_t bBase = aBase + S_A_SZ;
        #pragma unroll
        for (int ks = 0; ks < 4; ks++) {
            const int ch = ((2 * ks + cIdx) ^ xr) << 4;
            uint32_t aF[2][4], bF[2][4];
            #pragma unroll
            for (int mt = 0; mt < 2; mt++)
                LDSM4(aF[mt], aBase + (warpM + mt * 16 + rL) * 128 + ch);
            #pragma unroll
            for (int p = 0; p < 2; p++)
                LDSM4(bF[p], bBase + (warpN + p * 16 + rL) * 128 + ch);
            #pragma unroll
            for (int mt = 0; mt < 2; mt++)
                #pragma unroll
                for (int nt = 0; nt < 4; nt++) {
                    const int p = nt >> 1, sel = nt & 1;
                    MMA_TF32(acc[mt][nt], aF[mt], bF[p][sel], bF[p][sel + 2]);
                }
        }
    }

    float* part = g_spart[sl];
    const int lr = lane >> 2;
    const int lc = (lane & 3) * 2;
    #pragma unroll
    for (int mt = 0; mt < 2; mt++) {
        const int n0 = nBase + warpM + mt * 16 + lr;
        #pragma unroll
        for (int nt = 0; nt < 4; nt++) {
            const int col = mBase + warpN + nt * 8 + lc;
            if (col < Nc) {
                if (n0 < Nc) {
                    float2 v = make_float2(acc[mt][nt][0], acc[mt][nt][1]);
                    *reinterpret_cast<float2*>(&part[((size_t)(b * Nc + n0)) * 256 + col]) = v;
                }
                if (n0 + 8 < Nc) {
                    float2 v = make_float2(acc[mt][nt][2], acc[mt][nt][3]);
                    *reinterpret_cast<float2*>(&part[((size_t)(b * Nc + n0 + 8)) * 256 + col]) = v;
                }
            }
        }
    }
}

// ---- softmax: sum 4 partials, scale, softmax ------------------------------
__global__ __launch_bounds__(256) void softmax_kernel() {
    const int row = blockIdx.x;
    const int t = threadIdx.x;
    const float SC = 0.022097086912079608f;  // 1/sqrt(2048)
    __shared__ float red[256];
    float v = -1e30f;
    if (t < Nc) {
        float s = g_spart[0][(size_t)row * 256 + t] + g_spart[1][(size_t)row * 256 + t]
                + g_spart[2][(size_t)row * 256 + t] + g_spart[3][(size_t)row * 256 + t];
        v = s * SC;
    }
    red[t] = v;
    __syncthreads();
    #pragma unroll
    for (int s = 128; s > 0; s >>= 1) {
        if (t < s) red[t] = fmaxf(red[t], red[t + s]);
        __syncthreads();
    }
    float mx = red[0];
    __syncthreads();
    float e = (t < Nc) ? expf(v - mx) : 0.0f;
    red[t] = e;
    __syncthreads();
    #pragma unroll
    for (int s = 128; s > 0; s >>= 1) {
        if (t < s) red[t] += red[t + s];
        __syncthreads();
    }
    float inv = 1.0f / red[0];
    if (t < Nc) g_scores[(size_t)row * Nc + t] = e * inv;
}

// ---- out = attn @ lv (wmma) ----------------------------------------------
__global__ __launch_bounds__(128) void out_kernel(float* __restrict__ out) {
    const int b = blockIdx.z;
    const int nBase = blockIdx.y * 64;
    const int hBase = blockIdx.x * 64;
    const int tid = threadIdx.x;
    const int wid = tid >> 5;
    const int warpM = (wid >> 1) * 32;
    const int warpN = (wid & 1) * 32;
    __shared__ union {
        struct { float As[64][20]; float Bs[16][68]; } ld;
        float out[64][64];
    } sm;
    wmma::fragment<wmma::accumulator, 16, 16, 8, float> cfr[2][2];
    #pragma unroll
    for (int i = 0; i < 2; i++)
        #pragma unroll
        for (int j = 0; j < 2; j++) wmma::fill_fragment(cfr[i][j], 0.0f);
    const float* attn = g_scores + (size_t)b * Nc * Nc;
    const float* lvb  = g_lv + (size_t)b * Nc * Hc;
    const int kTiles = (Nc + 15) / 16;
    for (int kt = 0; kt < kTiles; kt++) {
        #pragma unroll
        for (int i = 0; i < 2; i++) {
            int idx = tid + i * 128;
            int r = idx >> 2, c4 = (idx & 3) * 4;
            int n = nBase + r, k = kt * 16 + c4;
            float4 v = make_float4(0.f, 0.f, 0.f, 0.f);
            if (n < Nc && k < Nc) v = *reinterpret_cast<const float4*>(&attn[(size_t)n * Nc + k]);
            *reinterpret_cast<float4*>(&sm.ld.As[r][c4]) = v;
        }
        #pragma unroll
        for (int i = 0; i < 2; i++) {
            int idx = tid + i * 128;
            int r = idx >> 4, c4 = (idx & 15) * 4;
            int k = kt * 16 + r;
            float4 v = make_float4(0.f, 0.f, 0.f, 0.f);
            if (k < Nc) v = *reinterpret_cast<const float4*>(&lvb[(size_t)k * Hc + hBase + c4]);
            *reinterpret_cast<float4*>(&sm.ld.Bs[r][c4]) = v;
        }
        __syncthreads();
        #pragma unroll
        for (int ks = 0; ks < 2; ks++) {
            wmma::fragment<wmma::matrix_a, 16, 16, 8, wmma::precision::tf32, wmma::row_major> af[2];
            wmma::fragment<wmma::matrix_b, 16, 16, 8, wmma::precision::tf32, wmma::row_major> bf[2];
            #pragma unroll
            for (int i = 0; i < 2; i++) {
                wmma::load_matrix_sync(af[i], &sm.ld.As[warpM + i * 16][ks * 8], 20);
                #pragma unroll
                for (int t = 0; t < af[i].num_elements; t++) af[i].x[t] = wmma::__float_to_tf32(af[i].x[t]);
            }
            #pragma unroll
            for (int j = 0; j < 2; j++) {
                wmma::load_matrix_sync(bf[j], &sm.ld.Bs[ks * 8][warpN + j * 16], 68);
                #pragma unroll
                for (int t = 0; t < bf[j].num_elements; t++) bf[j].x[t] = wmma::__float_to_tf32(bf[j].x[t]);
            }
            #pragma unroll
            for (int i = 0; i < 2; i++)
                #pragma unroll
                for (int j = 0; j < 2; j++) wmma::mma_sync(cfr[i][j], af[i], bf[j], cfr[i][j]);
        }
        __syncthreads();
    }
    #pragma unroll
    for (int i = 0; i < 2; i++)
        #pragma unroll
        for (int j = 0; j < 2; j++)
            wmma::store_matrix_sync(&sm.out[warpM + i * 16][warpN + j * 16], cfr[i][j], 64, wmma::mem_row_major);
    __syncthreads();
    #pragma unroll
    for (int it = 0; it < 8; it++) {
        int fid = tid + it * 128;
        int r = fid >> 4, c4 = (fid & 15) * 4;
        int n = nBase + r;
        if (n < Nc)
            *reinterpret_cast<float4*>(&out[((size_t)b * Nc + n) * Hc + hBase + c4]) =
                *reinterpret_cast<float4*>(&sm.out[r][c4]);
    }
}

// ---------------------------------------------------------------------------
extern "C" void kernel_launch(void* const* d_in, const int* in_sizes, int n_in,
                              void* d_out, int out_size) {
    (void)in_sizes; (void)n_in; (void)out_size;
    XPtrs xp;
    xp.x[0] = (const float*)d_in[0];
    xp.x[1] = (const float*)d_in[1];
    xp.x[2] = (const float*)d_in[2];
    xp.x[3] = (const float*)d_in[3];
    WPtrs wp;
    wp.w[0] = (const float*)d_in[4];
    wp.w[1] = (const float*)d_in[6];
    wp.w[2] = (const float*)d_in[8];
    wp.w[3] = (const float*)d_in[10];
    wp.w[4] = (const float*)d_in[12];
    ProjArgs pa;
    pa.bias[0] = (const float*)d_in[5];
    pa.bias[1] = (const float*)d_in[7];
    pa.bias[2] = (const float*)d_in[9];
    pa.bias[3] = (const float*)d_in[11];
    pa.bias[4] = (const float*)d_in[13];
    const float* param = (const float*)d_in[14];

    cudaFuncSetAttribute(proj_mma, cudaFuncAttributeMaxDynamicSharedMemorySize, P_DYN);
    cudaFuncSetAttribute(scores_mma, cudaFuncAttributeMaxDynamicSharedMemorySize, S_DYN);

    round_x_kernel<<<dim3(MTOK * Dc / 4 / 256, 1, 4), 256>>>(xp);
    transW_kernel<<<dim3(Hc / 32, Dc / 32, 5), dim3(32, 8)>>>(wp);
    proj_mma<<<dim3(Hc / 128, XR_ROWS / 128, 5), 256, P_DYN>>>(pa);
    add_round_kernel<<<MTOK * Dc / 4 / 256, 256>>>(param);
    scores_mma<<<dim3(4, 4, Bc * 4), 128, S_DYN>>>();
    softmax_kernel<<<MTOK, 256>>>();
    out_kernel<<<dim3(Hc / 64, (Nc + 63) / 64, Bc), 128>>>((float*)d_out);
}

// round 12
// speedup vs baseline: 1.0815x; 1.0060x over previous
#include <cuda_runtime.h>
#include <mma.h>
#include <cstdint>
#include <math.h>

using namespace nvcuda;

namespace {
constexpr int Bc = 16;
constexpr int Nc = 200;
constexpr int Dc = 2048;
constexpr int Hc = 2048;
constexpr int MTOK = Bc * Nc;       // 3200
constexpr int XR_ROWS = 3328;       // 26*128 padded
constexpr int KC = Dc / 32;         // 64
constexpr int P_A_SZ = 128 * 128;   // 16 KB
constexpr int P_STAGE = 2 * P_A_SZ; // 32 KB
constexpr int P_DYN = 3 * P_STAGE;  // 96 KB
constexpr int SKC = 32;
constexpr int S_A_SZ = 64 * 128;    // 8 KB
constexpr int S_STAGE = 2 * S_A_SZ; // 16 KB
constexpr int S_DYN = 3 * S_STAGE;  // 48 KB
}

__device__ __align__(16) float g_xr[4][(size_t)XR_ROWS * Dc];
__device__ __align__(16) float g_wt[5][(size_t)Dc * Hc];
__device__ __align__(16) float g_lq  [(size_t)MTOK * Hc];
__device__ __align__(16) float g_lk  [(size_t)MTOK * Hc];
__device__ __align__(16) float g_lv  [(size_t)MTOK * Hc];
__device__ __align__(16) float g_lloc[(size_t)MTOK * Hc];
__device__ __align__(16) float g_kloc[(size_t)MTOK * Hc];
__device__ __align__(16) float g_a1  [(size_t)MTOK * Hc];
__device__ __align__(16) float g_a2  [(size_t)MTOK * Hc];
__device__ __align__(16) float g_spart[4][(size_t)MTOK * 256];
__device__ __align__(16) float g_scores[(size_t)Bc * Nc * Nc];

struct XPtrs { const float* x[4]; };
struct WPtrs { const float* w[5]; };
struct ProjArgs { const float* bias[5]; };

__device__ __forceinline__ uint32_t smem_u32(const void* p) {
    uint32_t a;
    asm("{ .reg .u64 t; cvta.to.shared.u64 t, %1; cvt.u32.u64 %0, t; }" : "=r"(a) : "l"(p));
    return a;
}
__device__ __forceinline__ float rna_tf32(float x) {
    float y; asm("cvt.rna.tf32.f32 %0, %1;" : "=f"(y) : "f"(x)); return y;
}
__device__ __forceinline__ void cp16_s(uint32_t d, const void* s) {
    asm volatile("cp.async.cg.shared.global [%0], [%1], 16;\n" :: "r"(d), "l"(s));
}
__device__ __forceinline__ void cp_commit() { asm volatile("cp.async.commit_group;\n"); }
template <int N> __device__ __forceinline__ void cp_wait() {
    asm volatile("cp.async.wait_group %0;\n" :: "n"(N));
}
#define LDSM4(d, addr) \
    asm volatile("ldmatrix.sync.aligned.m8n8.x4.shared.b16 {%0,%1,%2,%3}, [%4];" \
        : "=r"((d)[0]), "=r"((d)[1]), "=r"((d)[2]), "=r"((d)[3]) : "r"(addr))
#define MMA_TF32(c, a, b0v, b1v) \
    asm volatile("mma.sync.aligned.m16n8k8.row.col.f32.tf32.tf32.f32 " \
        "{%0,%1,%2,%3}, {%4,%5,%6,%7}, {%8,%9}, {%0,%1,%2,%3};" \
        : "+f"((c)[0]), "+f"((c)[1]), "+f"((c)[2]), "+f"((c)[3]) \
        : "r"((a)[0]), "r"((a)[1]), "r"((a)[2]), "r"((a)[3]), "r"(b0v), "r"(b1v))

// ---- prep: tf32-round X into padded scratch -------------------------------
__global__ __launch_bounds__(256) void round_x_kernel(XPtrs xp) {
    const int j = blockIdx.z;
    const float4* src = reinterpret_cast<const float4*>(xp.x[j]);
    float4* dst = reinterpret_cast<float4*>(g_xr[j]);
    const int idx = blockIdx.x * 256 + threadIdx.x;
    float4 v = src[idx];
    v.x = rna_tf32(v.x); v.y = rna_tf32(v.y); v.z = rna_tf32(v.z); v.w = rna_tf32(v.w);
    dst[idx] = v;
}

// ---- prep: W[k][n] -> Wt[n][k], tf32-rounded ------------------------------
__global__ __launch_bounds__(256) void transW_kernel(WPtrs wp) {
    __shared__ float t[32][33];
    const int j = blockIdx.z;
    const float* W = wp.w[j];
    float* Wt = g_wt[j];
    const int tx = threadIdx.x, ty = threadIdx.y;
    const int n0 = blockIdx.x * 32, k0 = blockIdx.y * 32;
    #pragma unroll
    for (int i = 0; i < 4; i++)
        t[ty + 8 * i][tx] = rna_tf32(W[(size_t)(k0 + ty + 8 * i) * Hc + n0 + tx]);
    __syncthreads();
    #pragma unroll
    for (int i = 0; i < 4; i++)
        Wt[(size_t)(n0 + ty + 8 * i) * Dc + k0 + tx] = t[tx][ty + 8 * i];
}

// ---- prep for scores: a1 = rna(lq+param), a2 = rna(lq+lloc) ---------------
__global__ __launch_bounds__(256) void add_round_kernel(const float* __restrict__ param) {
    const int idx = blockIdx.x * 256 + threadIdx.x;   // float4 index
    const float4 lq = reinterpret_cast<const float4*>(g_lq)[idx];
    const float4 pv = reinterpret_cast<const float4*>(param)[idx];
    const float4 ll = reinterpret_cast<const float4*>(g_lloc)[idx];
    float4 a1, a2;
    a1.x = rna_tf32(lq.x + pv.x); a1.y = rna_tf32(lq.y + pv.y);
    a1.z = rna_tf32(lq.z + pv.z); a1.w = rna_tf32(lq.w + pv.w);
    a2.x = rna_tf32(lq.x + ll.x); a2.y = rna_tf32(lq.y + ll.y);
    a2.z = rna_tf32(lq.z + ll.z); a2.w = rna_tf32(lq.w + ll.w);
    reinterpret_cast<float4*>(g_a1)[idx] = a1;
    reinterpret_cast<float4*>(g_a2)[idx] = a2;
}

// ---- tf32 mma.sync projection: 128x128 CTA, 4 warps, 64x64 warp tiles -----
// Zero LDSM redundancy: 8 LDSM feed 32 MMAs per warp-k8.
__global__ __launch_bounds__(128, 2) void proj_mma(ProjArgs pa) {
    extern __shared__ char dynraw[];
    const int z = blockIdx.z;
    const float* Xr = g_xr[z <= 2 ? z : 3];
    const float* Wt = g_wt[z];
    const float* bias = pa.bias[z];
    float* Y;
    switch (z) {
        case 0:  Y = g_lq;   break;
        case 1:  Y = g_lk;   break;
        case 2:  Y = g_lv;   break;
        case 3:  Y = g_lloc; break;
        default: Y = g_kloc; break;
    }
    const bool doRound = (z == 1) || (z == 4);   // lk, kloc consumed as tf32
    const int nBase = blockIdx.x * 128;
    const int mBase = blockIdx.y * 128;
    const int tid = threadIdx.x;
    const int wid = tid >> 5;            // 0..3
    const int lane = tid & 31;
    const int warpM = (wid & 1) * 64;    // 0 or 64
    const int warpN = (wid >> 1) * 64;   // 0 or 64
    const uint32_t smemBase = smem_u32(dynraw);

    const int rL = (lane & 7) + 8 * ((lane >> 3) & 1);   // 0-15
    const int cIdx = lane >> 4;                          // 0/1
    const int xr = rL & 7;

    auto load_stage = [&](int s, int kc) {
        const uint32_t base = smemBase + s * P_STAGE;
        const float* xs = Xr + (size_t)mBase * Dc + kc * 32;
        const float* ws = Wt + (size_t)nBase * Dc + kc * 32;
        #pragma unroll
        for (int i = 0; i < 8; i++) {
            int idx = tid + i * 128;
            int r = idx >> 3, j = idx & 7;
            cp16_s(base + r * 128 + ((j ^ (r & 7)) << 4), xs + (size_t)r * Dc + j * 4);
        }
        #pragma unroll
        for (int i = 0; i < 8; i++) {
            int idx = tid + i * 128;
            int r = idx >> 3, j = idx & 7;
            cp16_s(base + P_A_SZ + r * 128 + ((j ^ (r & 7)) << 4), ws + (size_t)r * Dc + j * 4);
        }
    };

    float acc[4][8][4];
    #pragma unroll
    for (int mt = 0; mt < 4; mt++)
        #pragma unroll
        for (int nt = 0; nt < 8; nt++)
            #pragma unroll
            for (int q = 0; q < 4; q++) acc[mt][nt][q] = 0.0f;

    load_stage(0, 0); cp_commit();
    load_stage(1, 1); cp_commit();

    for (int kc = 0; kc < KC; kc++) {
        const int s = kc % 3;
        cp_wait<1>();
        __syncthreads();
        if (kc + 2 < KC) load_stage((kc + 2) % 3, kc + 2);
        cp_commit();

        const uint32_t aBase = smemBase + s * P_STAGE;
        const uint32_t bBase = aBase + P_A_SZ;
        #pragma unroll
        for (int ks = 0; ks < 4; ks++) {
            const int ch = ((2 * ks + cIdx) ^ xr) << 4;
            uint32_t aF[4][4], bF[4][4];
            #pragma unroll
            for (int mt = 0; mt < 4; mt++)
                LDSM4(aF[mt], aBase + (warpM + mt * 16 + rL) * 128 + ch);
            #pragma unroll
            for (int p = 0; p < 4; p++)
                LDSM4(bF[p], bBase + (warpN + p * 16 + rL) * 128 + ch);
            #pragma unroll
            for (int mt = 0; mt < 4; mt++)
                #pragma unroll
                for (int nt = 0; nt < 8; nt++) {
                    const int p = nt >> 1, sel = nt & 1;
                    MMA_TF32(acc[mt][nt], aF[mt], bF[p][sel], bF[p][sel + 2]);
                }
        }
    }

    const int lr = lane >> 2;
    const int lc = (lane & 3) * 2;
    #pragma unroll
    for (int mt = 0; mt < 4; mt++) {
        const int r0 = mBase + warpM + mt * 16 + lr;
        #pragma unroll
        for (int nt = 0; nt < 8; nt++) {
            const int col = nBase + warpN + nt * 8 + lc;
            const float2 bv = *reinterpret_cast<const float2*>(&bias[col]);
            float2 v0 = make_float2(acc[mt][nt][0] + bv.x, acc[mt][nt][1] + bv.y);
            float2 v1 = make_float2(acc[mt][nt][2] + bv.x, acc[mt][nt][3] + bv.y);
            if (doRound) {
                v0.x = rna_tf32(v0.x); v0.y = rna_tf32(v0.y);
                v1.x = rna_tf32(v1.x); v1.y = rna_tf32(v1.y);
            }
            if (r0 < MTOK)
                *reinterpret_cast<float2*>(&Y[(size_t)r0 * Hc + col]) = v0;
            if (r0 + 8 < MTOK)
                *reinterpret_cast<float2*>(&Y[(size_t)(r0 + 8) * Hc + col]) = v1;
        }
    }
}

// ---- scores: split-K mma.sync (unchanged) ---------------------------------
__global__ __launch_bounds__(128, 1) void scores_mma() {
    extern __shared__ char dynraw[];
    const int b = blockIdx.z >> 2;
    const int sl = blockIdx.z & 3;
    const float* Asrc = (sl < 2 ? g_a1 : g_a2) + (size_t)b * Nc * Dc + (sl & 1) * 1024;
    const float* Bsrc = (sl < 2 ? g_lk : g_kloc) + (size_t)b * Nc * Dc + (sl & 1) * 1024;
    const int nBase = blockIdx.y * 64;
    const int mBase = blockIdx.x * 64;
    const int tid = threadIdx.x;
    const int wid = tid >> 5;
    const int lane = tid & 31;
    const int warpM = (wid >> 1) * 32;
    const int warpN = (wid & 1) * 32;
    const uint32_t smemBase = smem_u32(dynraw);

    const int rL = (lane & 7) + 8 * ((lane >> 3) & 1);
    const int cIdx = lane >> 4;
    const int xr = rL & 7;

    auto load_stage = [&](int s, int kc) {
        const uint32_t base = smemBase + s * S_STAGE;
        #pragma unroll
        for (int i = 0; i < 4; i++) {
            int idx = tid + i * 128;
            int r = idx >> 3, j = idx & 7;
            int row = nBase + r; if (row > Nc - 1) row = Nc - 1;
            cp16_s(base + r * 128 + ((j ^ (r & 7)) << 4),
                   Asrc + (size_t)row * Dc + kc * 32 + j * 4);
        }
        #pragma unroll
        for (int i = 0; i < 4; i++) {
            int idx = tid + i * 128;
            int r = idx >> 3, j = idx & 7;
            int row = mBase + r; if (row > Nc - 1) row = Nc - 1;
            cp16_s(base + S_A_SZ + r * 128 + ((j ^ (r & 7)) << 4),
                   Bsrc + (size_t)row * Dc + kc * 32 + j * 4);
        }
    };

    float acc[2][4][4];
    #pragma unroll
    for (int mt = 0; mt < 2; mt++)
        #pragma unroll
        for (int nt = 0; nt < 4; nt++)
            #pragma unroll
            for (int q = 0; q < 4; q++) acc[mt][nt][q] = 0.0f;

    load_stage(0, 0); cp_commit();
    load_stage(1, 1); cp_commit();

    for (int kc = 0; kc < SKC; kc++) {
        const int s = kc % 3;
        cp_wait<1>();
        __syncthreads();
        if (kc + 2 < SKC) load_stage((kc + 2) % 3, kc + 2);
        cp_commit();

        const uint32_t aBase = smemBase + s * S_STAGE;
        const uint32_t bBase = aBase + S_A_SZ;
        #pragma unroll
        for (int ks = 0; ks < 4; ks++) {
            const int ch = ((2 * ks + cIdx) ^ xr) << 4;
            uint32_t aF[2][4], bF[2][4];
            #pragma unroll
            for (int mt = 0; mt < 2; mt++)
                LDSM4(aF[mt], aBase + (warpM + mt * 16 + rL) * 128 + ch);
            #pragma unroll
            for (int p = 0; p < 2; p++)
                LDSM4(bF[p], bBase + (warpN + p * 16 + rL) * 128 + ch);
            #pragma unroll
            for (int mt = 0; mt < 2; mt++)
                #pragma unroll
                for (int nt = 0; nt < 4; nt++) {
                    const int p = nt >> 1, sel = nt & 1;
                    MMA_TF32(acc[mt][nt], aF[mt], bF[p][sel], bF[p][sel + 2]);
                }
        }
    }

    float* part = g_spart[sl];
    const int lr = lane >> 2;
    const int lc = (lane & 3) * 2;
    #pragma unroll
    for (int mt = 0; mt < 2; mt++) {
        const int n0 = nBase + warpM + mt * 16 + lr;
        #pragma unroll
        for (int nt = 0; nt < 4; nt++) {
            const int col = mBase + warpN + nt * 8 + lc;
            if (col < Nc) {
                if (n0 < Nc) {
                    float2 v = make_float2(acc[mt][nt][0], acc[mt][nt][1]);
                    *reinterpret_cast<float2*>(&part[((size_t)(b * Nc + n0)) * 256 + col]) = v;
                }
                if (n0 + 8 < Nc) {
                    float2 v = make_float2(acc[mt][nt][2], acc[mt][nt][3]);
                    *reinterpret_cast<float2*>(&part[((size_t)(b * Nc + n0 + 8)) * 256 + col]) = v;
                }
            }
        }
    }
}

// ---- softmax: sum 4 partials, scale, softmax ------------------------------
__global__ __launch_bounds__(256) void softmax_kernel() {
    const int row = blockIdx.x;
    const int t = threadIdx.x;
    const float SC = 0.022097086912079608f;  // 1/sqrt(2048)
    __shared__ float red[256];
    float v = -1e30f;
    if (t < Nc) {
        float s = g_spart[0][(size_t)row * 256 + t] + g_spart[1][(size_t)row * 256 + t]
                + g_spart[2][(size_t)row * 256 + t] + g_spart[3][(size_t)row * 256 + t];
        v = s * SC;
    }
    red[t] = v;
    __syncthreads();
    #pragma unroll
    for (int s = 128; s > 0; s >>= 1) {
        if (t < s) red[t] = fmaxf(red[t], red[t + s]);
        __syncthreads();
    }
    float mx = red[0];
    __syncthreads();
    float e = (t < Nc) ? expf(v - mx) : 0.0f;
    red[t] = e;
    __syncthreads();
    #pragma unroll
    for (int s = 128; s > 0; s >>= 1) {
        if (t < s) red[t] += red[t + s];
        __syncthreads();
    }
    float inv = 1.0f / red[0];
    if (t < Nc) g_scores[(size_t)row * Nc + t] = e * inv;
}

// ---- out = attn @ lv (wmma) ----------------------------------------------
__global__ __launch_bounds__(128) void out_kernel(float* __restrict__ out) {
    const int b = blockIdx.z;
    const int nBase = blockIdx.y * 64;
    const int hBase = blockIdx.x * 64;
    const int tid = threadIdx.x;
    const int wid = tid >> 5;
    const int warpM = (wid >> 1) * 32;
    const int warpN = (wid & 1) * 32;
    __shared__ union {
        struct { float As[64][20]; float Bs[16][68]; } ld;
        float out[64][64];
    } sm;
    wmma::fragment<wmma::accumulator, 16, 16, 8, float> cfr[2][2];
    #pragma unroll
    for (int i = 0; i < 2; i++)
        #pragma unroll
        for (int j = 0; j < 2; j++) wmma::fill_fragment(cfr[i][j], 0.0f);
    const float* attn = g_scores + (size_t)b * Nc * Nc;
    const float* lvb  = g_lv + (size_t)b * Nc * Hc;
    const int kTiles = (Nc + 15) / 16;
    for (int kt = 0; kt < kTiles; kt++) {
        #pragma unroll
        for (int i = 0; i < 2; i++) {
            int idx = tid + i * 128;
            int r = idx >> 2, c4 = (idx & 3) * 4;
            int n = nBase + r, k = kt * 16 + c4;
            float4 v = make_float4(0.f, 0.f, 0.f, 0.f);
            if (n < Nc && k < Nc) v = *reinterpret_cast<const float4*>(&attn[(size_t)n * Nc + k]);
            *reinterpret_cast<float4*>(&sm.ld.As[r][c4]) = v;
        }
        #pragma unroll
        for (int i = 0; i < 2; i++) {
            int idx = tid + i * 128;
            int r = idx >> 4, c4 = (idx & 15) * 4;
            int k = kt * 16 + r;
            float4 v = make_float4(0.f, 0.f, 0.f, 0.f);
            if (k < Nc) v = *reinterpret_cast<const float4*>(&lvb[(size_t)k * Hc + hBase + c4]);
            *reinterpret_cast<float4*>(&sm.ld.Bs[r][c4]) = v;
        }
        __syncthreads();
        #pragma unroll
        for (int ks = 0; ks < 2; ks++) {
            wmma::fragment<wmma::matrix_a, 16, 16, 8, wmma::precision::tf32, wmma::row_major> af[2];
            wmma::fragment<wmma::matrix_b, 16, 16, 8, wmma::precision::tf32, wmma::row_major> bf[2];
            #pragma unroll
            for (int i = 0; i < 2; i++) {
                wmma::load_matrix_sync(af[i], &sm.ld.As[warpM + i * 16][ks * 8], 20);
                #pragma unroll
                for (int t = 0; t < af[i].num_elements; t++) af[i].x[t] = wmma::__float_to_tf32(af[i].x[t]);
            }
            #pragma unroll
            for (int j = 0; j < 2; j++) {
                wmma::load_matrix_sync(bf[j], &sm.ld.Bs[ks * 8][warpN + j * 16], 68);
                #pragma unroll
                for (int t = 0; t < bf[j].num_elements; t++) bf[j].x[t] = wmma::__float_to_tf32(bf[j].x[t]);
            }
            #pragma unroll
            for (int i = 0; i < 2; i++)
                #pragma unroll
                for (int j = 0; j < 2; j++) wmma::mma_sync(cfr[i][j], af[i], bf[j], cfr[i][j]);
        }
        __syncthreads();
    }
    #pragma unroll
    for (int i = 0; i < 2; i++)
        #pragma unroll
        for (int j = 0; j < 2; j++)
            wmma::store_matrix_sync(&sm.out[warpM + i * 16][warpN + j * 16], cfr[i][j], 64, wmma::mem_row_major);
    __syncthreads();
    #pragma unroll
    for (int it = 0; it < 8; it++) {
        int fid = tid + it * 128;
        int r = fid >> 4, c4 = (fid & 15) * 4;
        int n = nBase + r;
        if (n < Nc)
            *reinterpret_cast<float4*>(&out[((size_t)b * Nc + n) * Hc + hBase + c4]) =
                *reinterpret_cast<float4*>(&sm.out[r][c4]);
    }
}

// ---------------------------------------------------------------------------
extern "C" void kernel_launch(void* const* d_in, const int* in_sizes, int n_in,
                              void* d_out, int out_size) {
    (void)in_sizes; (void)n_in; (void)out_size;
    XPtrs xp;
    xp.x[0] = (const float*)d_in[0];
    xp.x[1] = (const float*)d_in[1];
    xp.x[2] = (const float*)d_in[2];
    xp.x[3] = (const float*)d_in[3];
    WPtrs wp;
    wp.w[0] = (const float*)d_in[4];
    wp.w[1] = (const float*)d_in[6];
    wp.w[2] = (const float*)d_in[8];
    wp.w[3] = (const float*)d_in[10];
    wp.w[4] = (const float*)d_in[12];
    ProjArgs pa;
    pa.bias[0] = (const float*)d_in[5];
    pa.bias[1] = (const float*)d_in[7];
    pa.bias[2] = (const float*)d_in[9];
    pa.bias[3] = (const float*)d_in[11];
    pa.bias[4] = (const float*)d_in[13];
    const float* param = (const float*)d_in[14];

    cudaFuncSetAttribute(proj_mma, cudaFuncAttributeMaxDynamicSharedMemorySize, P_DYN);
    cudaFuncSetAttribute(scores_mma, cudaFuncAttributeMaxDynamicSharedMemorySize, S_DYN);

    round_x_kernel<<<dim3(MTOK * Dc / 4 / 256, 1, 4), 256>>>(xp);
    transW_kernel<<<dim3(Hc / 32, Dc / 32, 5), dim3(32, 8)>>>(wp);
    proj_mma<<<dim3(Hc / 128, XR_ROWS / 128, 5), 128, P_DYN>>>(pa);
    add_round_kernel<<<MTOK * Dc / 4 / 256, 256>>>(param);
    scores_mma<<<dim3(4, 4, Bc * 4), 128, S_DYN>>>();
    softmax_kernel<<<MTOK, 256>>>();
    out_kernel<<<dim3(Hc / 64, (Nc + 63) / 64, Bc), 128>>>((float*)d_out);
}

// round 13
// speedup vs baseline: 1.7575x; 1.6250x over previous
#include <cuda_runtime.h>
#include <cuda_fp16.h>
#include <mma.h>
#include <cstdint>
#include <math.h>

using namespace nvcuda;

namespace {
constexpr int Bc = 16;
constexpr int Nc = 200;
constexpr int Dc = 2048;
constexpr int Hc = 2048;
constexpr int MTOK = Bc * Nc;       // 3200
constexpr int XR_ROWS = 3328;       // 26*128 padded
constexpr int KC = Dc / 64;         // 32 k-chunks of 64 halves (128B rows)
constexpr int P_A_SZ = 128 * 128;   // 16 KB (128 rows x 128B)
constexpr int P_STAGE = 2 * P_A_SZ; // 32 KB
constexpr int P_DYN = 3 * P_STAGE;  // 96 KB
constexpr int SKC = 16;             // 1024 / 64
constexpr int S_A_SZ = 64 * 128;    // 8 KB
constexpr int S_STAGE = 2 * S_A_SZ; // 16 KB
constexpr int S_DYN = 3 * S_STAGE;  // 48 KB
}

__device__ __align__(16) __half g_xh[4][(size_t)XR_ROWS * Dc];
__device__ __align__(16) __half g_wth[5][(size_t)Dc * Hc];
__device__ __align__(16) float  g_lq  [(size_t)MTOK * Hc];
__device__ __align__(16) float  g_lv  [(size_t)MTOK * Hc];
__device__ __align__(16) float  g_lloc[(size_t)MTOK * Hc];
__device__ __align__(16) __half g_lkh  [(size_t)MTOK * Hc];
__device__ __align__(16) __half g_kloch[(size_t)MTOK * Hc];
__device__ __align__(16) __half g_a1h  [(size_t)MTOK * Hc];
__device__ __align__(16) __half g_a2h  [(size_t)MTOK * Hc];
__device__ __align__(16) float  g_spart[4][(size_t)MTOK * 256];
__device__ __align__(16) float  g_scores[(size_t)Bc * Nc * Nc];

struct XPtrs { const float* x[4]; };
struct WPtrs { const float* w[5]; };
struct ProjArgs { const float* bias[5]; };

__device__ __forceinline__ uint32_t smem_u32(const void* p) {
    uint32_t a;
    asm("{ .reg .u64 t; cvta.to.shared.u64 t, %1; cvt.u32.u64 %0, t; }" : "=r"(a) : "l"(p));
    return a;
}
__device__ __forceinline__ void cp16_s(uint32_t d, const void* s) {
    asm volatile("cp.async.cg.shared.global [%0], [%1], 16;\n" :: "r"(d), "l"(s));
}
__device__ __forceinline__ void cp_commit() { asm volatile("cp.async.commit_group;\n"); }
template <int N> __device__ __forceinline__ void cp_wait() {
    asm volatile("cp.async.wait_group %0;\n" :: "n"(N));
}
#define LDSM4(d, addr) \
    asm volatile("ldmatrix.sync.aligned.m8n8.x4.shared.b16 {%0,%1,%2,%3}, [%4];" \
        : "=r"((d)[0]), "=r"((d)[1]), "=r"((d)[2]), "=r"((d)[3]) : "r"(addr))
// m16n8k16 f16: A = 4 regs, B = 2 regs (k0-7 reg, k8-15 reg), C/D = 4 f32
#define MMA_F16(c, a, b0v, b1v) \
    asm volatile("mma.sync.aligned.m16n8k16.row.col.f32.f16.f16.f32 " \
        "{%0,%1,%2,%3}, {%4,%5,%6,%7}, {%8,%9}, {%0,%1,%2,%3};" \
        : "+f"((c)[0]), "+f"((c)[1]), "+f"((c)[2]), "+f"((c)[3]) \
        : "r"((a)[0]), "r"((a)[1]), "r"((a)[2]), "r"((a)[3]), "r"(b0v), "r"(b1v))

// ---- prep: X f32 -> half into padded scratch ------------------------------
__global__ __launch_bounds__(256) void round_x_kernel(XPtrs xp) {
    const int j = blockIdx.z;
    const float4* src = reinterpret_cast<const float4*>(xp.x[j]);
    __half2* dst = reinterpret_cast<__half2*>(g_xh[j]);
    const int idx = blockIdx.x * 256 + threadIdx.x;
    float4 v = src[idx];
    dst[idx * 2]     = __floats2half2_rn(v.x, v.y);
    dst[idx * 2 + 1] = __floats2half2_rn(v.z, v.w);
}

// ---- prep: W[k][n] -> Wt[n][k] half ---------------------------------------
__global__ __launch_bounds__(256) void transW_kernel(WPtrs wp) {
    __shared__ float t[32][33];
    const int j = blockIdx.z;
    const float* W = wp.w[j];
    __half* Wt = g_wth[j];
    const int tx = threadIdx.x, ty = threadIdx.y;
    const int n0 = blockIdx.x * 32, k0 = blockIdx.y * 32;
    #pragma unroll
    for (int i = 0; i < 4; i++)
        t[ty + 8 * i][tx] = W[(size_t)(k0 + ty + 8 * i) * Hc + n0 + tx];
    __syncthreads();
    #pragma unroll
    for (int i = 0; i < 4; i++)
        Wt[(size_t)(n0 + ty + 8 * i) * Dc + k0 + tx] = __float2half(t[tx][ty + 8 * i]);
}

// ---- prep for scores: a1 = h(lq+param), a2 = h(lq+lloc) -------------------
__global__ __launch_bounds__(256) void add_round_kernel(const float* __restrict__ param) {
    const int idx = blockIdx.x * 256 + threadIdx.x;   // float4 index
    const float4 lq = reinterpret_cast<const float4*>(g_lq)[idx];
    const float4 pv = reinterpret_cast<const float4*>(param)[idx];
    const float4 ll = reinterpret_cast<const float4*>(g_lloc)[idx];
    __half2* a1 = reinterpret_cast<__half2*>(g_a1h);
    __half2* a2 = reinterpret_cast<__half2*>(g_a2h);
    a1[idx * 2]     = __floats2half2_rn(lq.x + pv.x, lq.y + pv.y);
    a1[idx * 2 + 1] = __floats2half2_rn(lq.z + pv.z, lq.w + pv.w);
    a2[idx * 2]     = __floats2half2_rn(lq.x + ll.x, lq.y + ll.y);
    a2[idx * 2 + 1] = __floats2half2_rn(lq.z + ll.z, lq.w + ll.w);
}

// ---- f16 mma.sync projection: 128x128 CTA, 4 warps, 64x64 warp tiles ------
__global__ __launch_bounds__(128, 2) void proj_mma(ProjArgs pa) {
    extern __shared__ char dynraw[];
    const int z = blockIdx.z;
    const __half* Xh = g_xh[z <= 2 ? z : 3];
    const __half* Wt = g_wth[z];
    const float* bias = pa.bias[z];
    float* Yf = nullptr;
    __half* Yh = nullptr;
    switch (z) {
        case 0:  Yf = g_lq;    break;
        case 1:  Yh = g_lkh;   break;
        case 2:  Yf = g_lv;    break;
        case 3:  Yf = g_lloc;  break;
        default: Yh = g_kloch; break;
    }
    const int nBase = blockIdx.x * 128;
    const int mBase = blockIdx.y * 128;
    const int tid = threadIdx.x;
    const int lane = tid & 31;
    const int wid = tid >> 5;
    const int warpM = (wid & 1) * 64;
    const int warpN = (wid >> 1) * 64;
    const uint32_t smemBase = smem_u32(dynraw);

    const int rL = (lane & 7) + 8 * ((lane >> 3) & 1);   // 0-15
    const int cIdx = lane >> 4;                          // 0/1 (16B = k8)
    const int xr = rL & 7;

    auto load_stage = [&](int s, int kc) {
        const uint32_t base = smemBase + s * P_STAGE;
        const __half* xs = Xh + (size_t)mBase * Dc + kc * 64;
        const __half* ws = Wt + (size_t)nBase * Dc + kc * 64;
        #pragma unroll
        for (int i = 0; i < 8; i++) {
            int idx = tid + i * 128;
            int r = idx >> 3, j = idx & 7;
            cp16_s(base + r * 128 + ((j ^ (r & 7)) << 4), xs + (size_t)r * Dc + j * 8);
        }
        #pragma unroll
        for (int i = 0; i < 8; i++) {
            int idx = tid + i * 128;
            int r = idx >> 3, j = idx & 7;
            cp16_s(base + P_A_SZ + r * 128 + ((j ^ (r & 7)) << 4), ws + (size_t)r * Dc + j * 8);
        }
    };

    float acc[4][8][4];
    #pragma unroll
    for (int mt = 0; mt < 4; mt++)
        #pragma unroll
        for (int nt = 0; nt < 8; nt++)
            #pragma unroll
            for (int q = 0; q < 4; q++) acc[mt][nt][q] = 0.0f;

    load_stage(0, 0); cp_commit();
    load_stage(1, 1); cp_commit();

    for (int kc = 0; kc < KC; kc++) {
        const int s = kc % 3;
        cp_wait<1>();
        __syncthreads();
        if (kc + 2 < KC) load_stage((kc + 2) % 3, kc + 2);
        cp_commit();

        const uint32_t aBase = smemBase + s * P_STAGE;
        const uint32_t bBase = aBase + P_A_SZ;
        #pragma unroll
        for (int ks = 0; ks < 4; ks++) {          // k16 per step
            const int ch = ((2 * ks + cIdx) ^ xr) << 4;
            uint32_t aF[4][4], bF[4][4];
            #pragma unroll
            for (int mt = 0; mt < 4; mt++)
                LDSM4(aF[mt], aBase + (warpM + mt * 16 + rL) * 128 + ch);
            #pragma unroll
            for (int p = 0; p < 4; p++)
                LDSM4(bF[p], bBase + (warpN + p * 16 + rL) * 128 + ch);
            #pragma unroll
            for (int mt = 0; mt < 4; mt++)
                #pragma unroll
                for (int nt = 0; nt < 8; nt++) {
                    const int p = nt >> 1, sel = nt & 1;
                    MMA_F16(acc[mt][nt], aF[mt], bF[p][sel], bF[p][sel + 2]);
                }
        }
    }

    const int lr = lane >> 2;
    const int lc = (lane & 3) * 2;
    #pragma unroll
    for (int mt = 0; mt < 4; mt++) {
        const int r0 = mBase + warpM + mt * 16 + lr;
        #pragma unroll
        for (int nt = 0; nt < 8; nt++) {
            const int col = nBase + warpN + nt * 8 + lc;
            const float2 bv = *reinterpret_cast<const float2*>(&bias[col]);
            float2 v0 = make_float2(acc[mt][nt][0] + bv.x, acc[mt][nt][1] + bv.y);
            float2 v1 = make_float2(acc[mt][nt][2] + bv.x, acc[mt][nt][3] + bv.y);
            if (Yh) {
                if (r0 < MTOK)
                    *reinterpret_cast<__half2*>(&Yh[(size_t)r0 * Hc + col]) =
                        __floats2half2_rn(v0.x, v0.y);
                if (r0 + 8 < MTOK)
                    *reinterpret_cast<__half2*>(&Yh[(size_t)(r0 + 8) * Hc + col]) =
                        __floats2half2_rn(v1.x, v1.y);
            } else {
                if (r0 < MTOK)
                    *reinterpret_cast<float2*>(&Yf[(size_t)r0 * Hc + col]) = v0;
                if (r0 + 8 < MTOK)
                    *reinterpret_cast<float2*>(&Yf[(size_t)(r0 + 8) * Hc + col]) = v1;
            }
        }
    }
}

// ---- scores: split-K f16 mma.sync -----------------------------------------
__global__ __launch_bounds__(128, 1) void scores_mma() {
    extern __shared__ char dynraw[];
    const int b = blockIdx.z >> 2;
    const int sl = blockIdx.z & 3;
    const __half* Asrc = (sl < 2 ? g_a1h : g_a2h) + (size_t)b * Nc * Dc + (sl & 1) * 1024;
    const __half* Bsrc = (sl < 2 ? g_lkh : g_kloch) + (size_t)b * Nc * Dc + (sl & 1) * 1024;
    const int nBase = blockIdx.y * 64;
    const int mBase = blockIdx.x * 64;
    const int tid = threadIdx.x;
    const int wid = tid >> 5;
    const int lane = tid & 31;
    const int warpM = (wid >> 1) * 32;
    const int warpN = (wid & 1) * 32;
    const uint32_t smemBase = smem_u32(dynraw);

    const int rL = (lane & 7) + 8 * ((lane >> 3) & 1);
    const int cIdx = lane >> 4;
    const int xr = rL & 7;

    auto load_stage = [&](int s, int kc) {
        const uint32_t base = smemBase + s * S_STAGE;
        #pragma unroll
        for (int i = 0; i < 4; i++) {
            int idx = tid + i * 128;
            int r = idx >> 3, j = idx & 7;
            int row = nBase + r; if (row > Nc - 1) row = Nc - 1;
            cp16_s(base + r * 128 + ((j ^ (r & 7)) << 4),
                   Asrc + (size_t)row * Dc + kc * 64 + j * 8);
        }
        #pragma unroll
        for (int i = 0; i < 4; i++) {
            int idx = tid + i * 128;
            int r = idx >> 3, j = idx & 7;
            int row = mBase + r; if (row > Nc - 1) row = Nc - 1;
            cp16_s(base + S_A_SZ + r * 128 + ((j ^ (r & 7)) << 4),
                   Bsrc + (size_t)row * Dc + kc * 64 + j * 8);
        }
    };

    float acc[2][4][4];
    #pragma unroll
    for (int mt = 0; mt < 2; mt++)
        #pragma unroll
        for (int nt = 0; nt < 4; nt++)
            #pragma unroll
            for (int q = 0; q < 4; q++) acc[mt][nt][q] = 0.0f;

    load_stage(0, 0); cp_commit();
    load_stage(1, 1); cp_commit();

    for (int kc = 0; kc < SKC; kc++) {
        const int s = kc % 3;
        cp_wait<1>();
        __syncthreads();
        if (kc + 2 < SKC) load_stage((kc + 2) % 3, kc + 2);
        cp_commit();

        const uint32_t aBase = smemBase + s * S_STAGE;
        const uint32_t bBase = aBase + S_A_SZ;
        #pragma unroll
        for (int ks = 0; ks < 4; ks++) {
            const int ch = ((2 * ks + cIdx) ^ xr) << 4;
            uint32_t aF[2][4], bF[2][4];
            #pragma unroll
            for (int mt = 0; mt < 2; mt++)
                LDSM4(aF[mt], aBase + (warpM + mt * 16 + rL) * 128 + ch);
            #pragma unroll
            for (int p = 0; p < 2; p++)
                LDSM4(bF[p], bBase + (warpN + p * 16 + rL) * 128 + ch);
            #pragma unroll
            for (int mt = 0; mt < 2; mt++)
                #pragma unroll
                for (int nt = 0; nt < 4; nt++) {
                    const int p = nt >> 1, sel = nt & 1;
                    MMA_F16(acc[mt][nt], aF[mt], bF[p][sel], bF[p][sel + 2]);
                }
        }
    }

    float* part = g_spart[sl];
    const int lr = lane >> 2;
    const int lc = (lane & 3) * 2;
    #pragma unroll
    for (int mt = 0; mt < 2; mt++) {
        const int n0 = nBase + warpM + mt * 16 + lr;
        #pragma unroll
        for (int nt = 0; nt < 4; nt++) {
            const int col = mBase + warpN + nt * 8 + lc;
            if (col < Nc) {
                if (n0 < Nc) {
                    float2 v = make_float2(acc[mt][nt][0], acc[mt][nt][1]);
                    *reinterpret_cast<float2*>(&part[((size_t)(b * Nc + n0)) * 256 + col]) = v;
                }
                if (n0 + 8 < Nc) {
                    float2 v = make_float2(acc[mt][nt][2], acc[mt][nt][3]);
                    *reinterpret_cast<float2*>(&part[((size_t)(b * Nc + n0 + 8)) * 256 + col]) = v;
                }
            }
        }
    }
}

// ---- softmax: sum 4 partials, scale, softmax ------------------------------
__global__ __launch_bounds__(256) void softmax_kernel() {
    const int row = blockIdx.x;
    const int t = threadIdx.x;
    const float SC = 0.022097086912079608f;  // 1/sqrt(2048)
    __shared__ float red[256];
    float v = -1e30f;
    if (t < Nc) {
        float s = g_spart[0][(size_t)row * 256 + t] + g_spart[1][(size_t)row * 256 + t]
                + g_spart[2][(size_t)row * 256 + t] + g_spart[3][(size_t)row * 256 + t];
        v = s * SC;
    }
    red[t] = v;
    __syncthreads();
    #pragma unroll
    for (int s = 128; s > 0; s >>= 1) {
        if (t < s) red[t] = fmaxf(red[t], red[t + s]);
        __syncthreads();
    }
    float mx = red[0];
    __syncthreads();
    float e = (t < Nc) ? expf(v - mx) : 0.0f;
    red[t] = e;
    __syncthreads();
    #pragma unroll
    for (int s = 128; s > 0; s >>= 1) {
        if (t < s) red[t] += red[t + s];
        __syncthreads();
    }
    float inv = 1.0f / red[0];
    if (t < Nc) g_scores[(size_t)row * Nc + t] = e * inv;
}

// ---- out = attn @ lv (wmma tf32, unchanged) -------------------------------
__global__ __launch_bounds__(128) void out_kernel(float* __restrict__ out) {
    const int b = blockIdx.z;
    const int nBase = blockIdx.y * 64;
    const int hBase = blockIdx.x * 64;
    const int tid = threadIdx.x;
    const int wid = tid >> 5;
    const int warpM = (wid >> 1) * 32;
    const int warpN = (wid & 1) * 32;
    __shared__ union {
        struct { float As[64][20]; float Bs[16][68]; } ld;
        float out[64][64];
    } sm;
    wmma::fragment<wmma::accumulator, 16, 16, 8, float> cfr[2][2];
    #pragma unroll
    for (int i = 0; i < 2; i++)
        #pragma unroll
        for (int j = 0; j < 2; j++) wmma::fill_fragment(cfr[i][j], 0.0f);
    const float* attn = g_scores + (size_t)b * Nc * Nc;
    const float* lvb  = g_lv + (size_t)b * Nc * Hc;
    const int kTiles = (Nc + 15) / 16;
    for (int kt = 0; kt < kTiles; kt++) {
        #pragma unroll
        for (int i = 0; i < 2; i++) {
            int idx = tid + i * 128;
            int r = idx >> 2, c4 = (idx & 3) * 4;
            int n = nBase + r, k = kt * 16 + c4;
            float4 v = make_float4(0.f, 0.f, 0.f, 0.f);
            if (n < Nc && k < Nc) v = *reinterpret_cast<const float4*>(&attn[(size_t)n * Nc + k]);
            *reinterpret_cast<float4*>(&sm.ld.As[r][c4]) = v;
        }
        #pragma unroll
        for (int i = 0; i < 2; i++) {
            int idx = tid + i * 128;
            int r = idx >> 4, c4 = (idx & 15) * 4;
            int k = kt * 16 + r;
            float4 v = make_float4(0.f, 0.f, 0.f, 0.f);
            if (k < Nc) v = *reinterpret_cast<const float4*>(&lvb[(size_t)k * Hc + hBase + c4]);
            *reinterpret_cast<float4*>(&sm.ld.Bs[r][c4]) = v;
        }
        __syncthreads();
        #pragma unroll
        for (int ks = 0; ks < 2; ks++) {
            wmma::fragment<wmma::matrix_a, 16, 16, 8, wmma::precision::tf32, wmma::row_major> af[2];
            wmma::fragment<wmma::matrix_b, 16, 16, 8, wmma::precision::tf32, wmma::row_major> bf[2];
            #pragma unroll
            for (int i = 0; i < 2; i++) {
                wmma::load_matrix_sync(af[i], &sm.ld.As[warpM + i * 16][ks * 8], 20);
                #pragma unroll
                for (int t = 0; t < af[i].num_elements; t++) af[i].x[t] = wmma::__float_to_tf32(af[i].x[t]);
            }
            #pragma unroll
            for (int j = 0; j < 2; j++) {
                wmma::load_matrix_sync(bf[j], &sm.ld.Bs[ks * 8][warpN + j * 16], 68);
                #pragma unroll
                for (int t = 0; t < bf[j].num_elements; t++) bf[j].x[t] = wmma::__float_to_tf32(bf[j].x[t]);
            }
            #pragma unroll
            for (int i = 0; i < 2; i++)
                #pragma unroll
                for (int j = 0; j < 2; j++) wmma::mma_sync(cfr[i][j], af[i], bf[j], cfr[i][j]);
        }
        __syncthreads();
    }
    #pragma unroll
    for (int i = 0; i < 2; i++)
        #pragma unroll
        for (int j = 0; j < 2; j++)
            wmma::store_matrix_sync(&sm.out[warpM + i * 16][warpN + j * 16], cfr[i][j], 64, wmma::mem_row_major);
    __syncthreads();
    #pragma unroll
    for (int it = 0; it < 8; it++) {
        int fid = tid + it * 128;
        int r = fid >> 4, c4 = (fid & 15) * 4;
        int n = nBase + r;
        if (n < Nc)
            *reinterpret_cast<float4*>(&out[((size_t)b * Nc + n) * Hc + hBase + c4]) =
                *reinterpret_cast<float4*>(&sm.out[r][c4]);
    }
}

// ---------------------------------------------------------------------------
extern "C" void kernel_launch(void* const* d_in, const int* in_sizes, int n_in,
                              void* d_out, int out_size) {
    (void)in_sizes; (void)n_in; (void)out_size;
    XPtrs xp;
    xp.x[0] = (const float*)d_in[0];
    xp.x[1] = (const float*)d_in[1];
    xp.x[2] = (const float*)d_in[2];
    xp.x[3] = (const float*)d_in[3];
    WPtrs wp;
    wp.w[0] = (const float*)d_in[4];
    wp.w[1] = (const float*)d_in[6];
    wp.w[2] = (const float*)d_in[8];
    wp.w[3] = (const float*)d_in[10];
    wp.w[4] = (const float*)d_in[12];
    ProjArgs pa;
    pa.bias[0] = (const float*)d_in[5];
    pa.bias[1] = (const float*)d_in[7];
    pa.bias[2] = (const float*)d_in[9];
    pa.bias[3] = (const float*)d_in[11];
    pa.bias[4] = (const float*)d_in[13];
    const float* param = (const float*)d_in[14];

    cudaFuncSetAttribute(proj_mma, cudaFuncAttributeMaxDynamicSharedMemorySize, P_DYN);
    cudaFuncSetAttribute(scores_mma, cudaFuncAttributeMaxDynamicSharedMemorySize, S_DYN);

    round_x_kernel<<<dim3(MTOK * Dc / 4 / 256, 1, 4), 256>>>(xp);
    transW_kernel<<<dim3(Hc / 32, Dc / 32, 5), dim3(32, 8)>>>(wp);
    proj_mma<<<dim3(Hc / 128, XR_ROWS / 128, 5), 128, P_DYN>>>(pa);
    add_round_kernel<<<MTOK * Dc / 4 / 256, 256>>>(param);
    scores_mma<<<dim3(4, 4, Bc * 4), 128, S_DYN>>>();
    softmax_kernel<<<MTOK, 256>>>();
    out_kernel<<<dim3(Hc / 64, (Nc + 63) / 64, Bc), 128>>>((float*)d_out);
}

// round 17
// speedup vs baseline: 1.7905x; 1.0188x over previous
#include <cuda_runtime.h>
#include <cuda_fp16.h>
#include <mma.h>
#include <cstdint>
#include <math.h>

using namespace nvcuda;

namespace {
constexpr int Bc = 16;
constexpr int Nc = 200;
constexpr int Dc = 2048;
constexpr int Hc = 2048;
constexpr int MTOK = Bc * Nc;       // 3200
constexpr int XR_ROWS = 3328;       // 13*256 padded
constexpr int KC = Dc / 64;         // 32 k-chunks of 64 halves (128B rows)
constexpr int P_A_SZ = 256 * 128;   // 32 KB (A: 256 rows x 128B)
constexpr int P_B_SZ = 128 * 128;   // 16 KB (B: 128 rows x 128B)
constexpr int P_STAGE = P_A_SZ + P_B_SZ;  // 48 KB
constexpr int P_DYN = 3 * P_STAGE;  // 144 KB
constexpr int SKC = 16;             // 1024 / 64
constexpr int S_A_SZ = 64 * 128;    // 8 KB
constexpr int S_STAGE = 2 * S_A_SZ; // 16 KB
constexpr int S_DYN = 3 * S_STAGE;  // 48 KB
}

__device__ __align__(16) __half g_xh[4][(size_t)XR_ROWS * Dc];
__device__ __align__(16) __half g_wth[5][(size_t)Dc * Hc];
__device__ __align__(16) float  g_lq  [(size_t)MTOK * Hc];
__device__ __align__(16) float  g_lloc[(size_t)MTOK * Hc];
__device__ __align__(16) __half g_lvh  [(size_t)MTOK * Hc];
__device__ __align__(16) __half g_lkh  [(size_t)MTOK * Hc];
__device__ __align__(16) __half g_kloch[(size_t)MTOK * Hc];
__device__ __align__(16) __half g_a1h  [(size_t)MTOK * Hc];
__device__ __align__(16) __half g_a2h  [(size_t)MTOK * Hc];
__device__ __align__(16) float  g_spart[4][(size_t)MTOK * 256];
__device__ __align__(16) __half g_scoresh[(size_t)Bc * Nc * Nc];

struct XPtrs { const float* x[4]; };
struct WPtrs { const float* w[5]; };
struct ProjArgs { const float* bias[5]; };

__device__ __forceinline__ uint32_t smem_u32(const void* p) {
    uint32_t a;
    asm("{ .reg .u64 t; cvta.to.shared.u64 t, %1; cvt.u32.u64 %0, t; }" : "=r"(a) : "l"(p));
    return a;
}
__device__ __forceinline__ void cp16_s(uint32_t d, const void* s) {
    asm volatile("cp.async.cg.shared.global [%0], [%1], 16;\n" :: "r"(d), "l"(s));
}
__device__ __forceinline__ void cp_commit() { asm volatile("cp.async.commit_group;\n"); }
template <int N> __device__ __forceinline__ void cp_wait() {
    asm volatile("cp.async.wait_group %0;\n" :: "n"(N));
}
#define LDSM4(d, addr) \
    asm volatile("ldmatrix.sync.aligned.m8n8.x4.shared.b16 {%0,%1,%2,%3}, [%4];" \
        : "=r"((d)[0]), "=r"((d)[1]), "=r"((d)[2]), "=r"((d)[3]) : "r"(addr))
#define MMA_F16(c, a, b0v, b1v) \
    asm volatile("mma.sync.aligned.m16n8k16.row.col.f32.f16.f16.f32 " \
        "{%0,%1,%2,%3}, {%4,%5,%6,%7}, {%8,%9}, {%0,%1,%2,%3};" \
        : "+f"((c)[0]), "+f"((c)[1]), "+f"((c)[2]), "+f"((c)[3]) \
        : "r"((a)[0]), "r"((a)[1]), "r"((a)[2]), "r"((a)[3]), "r"(b0v), "r"(b1v))

// ---- prep: X f32 -> half into padded scratch ------------------------------
__global__ __launch_bounds__(256) void round_x_kernel(XPtrs xp) {
    const int j = blockIdx.z;
    const float4* src = reinterpret_cast<const float4*>(xp.x[j]);
    __half2* dst = reinterpret_cast<__half2*>(g_xh[j]);
    const int idx = blockIdx.x * 256 + threadIdx.x;
    float4 v = src[idx];
    dst[idx * 2]     = __floats2half2_rn(v.x, v.y);
    dst[idx * 2 + 1] = __floats2half2_rn(v.z, v.w);
}

// ---- prep: W[k][n] -> Wt[n][k] half ---------------------------------------
__global__ __launch_bounds__(256) void transW_kernel(WPtrs wp) {
    __shared__ float t[32][33];
    const int j = blockIdx.z;
    const float* W = wp.w[j];
    __half* Wt = g_wth[j];
    const int tx = threadIdx.x, ty = threadIdx.y;
    const int n0 = blockIdx.x * 32, k0 = blockIdx.y * 32;
    #pragma unroll
    for (int i = 0; i < 4; i++)
        t[ty + 8 * i][tx] = W[(size_t)(k0 + ty + 8 * i) * Hc + n0 + tx];
    __syncthreads();
    #pragma unroll
    for (int i = 0; i < 4; i++)
        Wt[(size_t)(n0 + ty + 8 * i) * Dc + k0 + tx] = __float2half(t[tx][ty + 8 * i]);
}

// ---- prep for scores: a1 = h(lq+param), a2 = h(lq+lloc) -------------------
__global__ __launch_bounds__(256) void add_round_kernel(const float* __restrict__ param) {
    const int idx = blockIdx.x * 256 + threadIdx.x;   // float4 index
    const float4 lq = reinterpret_cast<const float4*>(g_lq)[idx];
    const float4 pv = reinterpret_cast<const float4*>(param)[idx];
    const float4 ll = reinterpret_cast<const float4*>(g_lloc)[idx];
    __half2* a1 = reinterpret_cast<__half2*>(g_a1h);
    __half2* a2 = reinterpret_cast<__half2*>(g_a2h);
    a1[idx * 2]     = __floats2half2_rn(lq.x + pv.x, lq.y + pv.y);
    a1[idx * 2 + 1] = __floats2half2_rn(lq.z + pv.z, lq.w + pv.w);
    a2[idx * 2]     = __floats2half2_rn(lq.x + ll.x, lq.y + ll.y);
    a2[idx * 2 + 1] = __floats2half2_rn(lq.z + ll.z, lq.w + ll.w);
}

// ---- f16 mma.sync projection: 256x128 CTA, 8 warps, 64x64 warp tiles ------
__global__ __launch_bounds__(256, 1) void proj_mma(ProjArgs pa) {
    extern __shared__ char dynraw[];
    const int z = blockIdx.z;
    const __half* Xh = g_xh[z <= 2 ? z : 3];
    const __half* Wt = g_wth[z];
    const float* bias = pa.bias[z];
    float* Yf = nullptr;
    __half* Yh = nullptr;
    switch (z) {
        case 0:  Yf = g_lq;    break;
        case 1:  Yh = g_lkh;   break;
        case 2:  Yh = g_lvh;   break;
        case 3:  Yf = g_lloc;  break;
        default: Yh = g_kloch; break;
    }
    const int nBase = blockIdx.x * 128;
    const int mBase = blockIdx.y * 256;
    const int tid = threadIdx.x;
    const int lane = tid & 31;
    const int wid = tid >> 5;            // 0..7
    const int warpM = (wid & 3) * 64;    // 0,64,128,192
    const int warpN = (wid >> 2) * 64;   // 0 or 64
    const uint32_t smemBase = smem_u32(dynraw);

    const int rL = (lane & 7) + 8 * ((lane >> 3) & 1);   // 0-15
    const int cIdx = lane >> 4;                          // 0/1 (16B = k8)
    const int xr = rL & 7;

    auto load_stage = [&](int s, int kc) {
        const uint32_t base = smemBase + s * P_STAGE;
        const __half* xs = Xh + (size_t)mBase * Dc + kc * 64;
        const __half* ws = Wt + (size_t)nBase * Dc + kc * 64;
        #pragma unroll
        for (int i = 0; i < 8; i++) {
            int idx = tid + i * 256;     // 2048 chunks: 256 rows x 8
            int r = idx >> 3, j = idx & 7;
            cp16_s(base + r * 128 + ((j ^ (r & 7)) << 4), xs + (size_t)r * Dc + j * 8);
        }
        #pragma unroll
        for (int i = 0; i < 4; i++) {
            int idx = tid + i * 256;     // 1024 chunks: 128 rows x 8
            int r = idx >> 3, j = idx & 7;
            cp16_s(base + P_A_SZ + r * 128 + ((j ^ (r & 7)) << 4), ws + (size_t)r * Dc + j * 8);
        }
    };

    float acc[4][8][4];
    #pragma unroll
    for (int mt = 0; mt < 4; mt++)
        #pragma unroll
        for (int nt = 0; nt < 8; nt++)
            #pragma unroll
            for (int q = 0; q < 4; q++) acc[mt][nt][q] = 0.0f;

    load_stage(0, 0); cp_commit();
    load_stage(1, 1); cp_commit();

    for (int kc = 0; kc < KC; kc++) {
        const int s = kc % 3;
        cp_wait<1>();
        __syncthreads();
        if (kc + 2 < KC) load_stage((kc + 2) % 3, kc + 2);
        cp_commit();

        const uint32_t aBase = smemBase + s * P_STAGE;
        const uint32_t bBase = aBase + P_A_SZ;
        #pragma unroll
        for (int ks = 0; ks < 4; ks++) {          // k16 per step
            const int ch = ((2 * ks + cIdx) ^ xr) << 4;
            uint32_t aF[4][4], bF[4][4];
            #pragma unroll
            for (int mt = 0; mt < 4; mt++)
                LDSM4(aF[mt], aBase + (warpM + mt * 16 + rL) * 128 + ch);
            #pragma unroll
            for (int p = 0; p < 4; p++)
                LDSM4(bF[p], bBase + (warpN + p * 16 + rL) * 128 + ch);
            #pragma unroll
            for (int mt = 0; mt < 4; mt++)
                #pragma unroll
                for (int nt = 0; nt < 8; nt++) {
                    const int p = nt >> 1, sel = nt & 1;
                    MMA_F16(acc[mt][nt], aF[mt], bF[p][sel], bF[p][sel + 2]);
                }
        }
    }

    const int lr = lane >> 2;
    const int lc = (lane & 3) * 2;
    #pragma unroll
    for (int mt = 0; mt < 4; mt++) {
        const int r0 = mBase + warpM + mt * 16 + lr;
        #pragma unroll
        for (int nt = 0; nt < 8; nt++) {
            const int col = nBase + warpN + nt * 8 + lc;
            const float2 bv = *reinterpret_cast<const float2*>(&bias[col]);
            float2 v0 = make_float2(acc[mt][nt][0] + bv.x, acc[mt][nt][1] + bv.y);
            float2 v1 = make_float2(acc[mt][nt][2] + bv.x, acc[mt][nt][3] + bv.y);
            if (Yh) {
                if (r0 < MTOK)
                    *reinterpret_cast<__half2*>(&Yh[(size_t)r0 * Hc + col]) =
                        __floats2half2_rn(v0.x, v0.y);
                if (r0 + 8 < MTOK)
                    *reinterpret_cast<__half2*>(&Yh[(size_t)(r0 + 8) * Hc + col]) =
                        __floats2half2_rn(v1.x, v1.y);
            } else {
                if (r0 < MTOK)
                    *reinterpret_cast<float2*>(&Yf[(size_t)r0 * Hc + col]) = v0;
                if (r0 + 8 < MTOK)
                    *reinterpret_cast<float2*>(&Yf[(size_t)(r0 + 8) * Hc + col]) = v1;
            }
        }
    }
}

// ---- scores: split-K f16 mma.sync (unchanged) -----------------------------
__global__ __launch_bounds__(128, 1) void scores_mma() {
    extern __shared__ char dynraw[];
    const int b = blockIdx.z >> 2;
    const int sl = blockIdx.z & 3;
    const __half* Asrc = (sl < 2 ? g_a1h : g_a2h) + (size_t)b * Nc * Dc + (sl & 1) * 1024;
    const __half* Bsrc = (sl < 2 ? g_lkh : g_kloch) + (size_t)b * Nc * Dc + (sl & 1) * 1024;
    const int nBase = blockIdx.y * 64;
    const int mBase = blockIdx.x * 64;
    const int tid = threadIdx.x;
    const int wid = tid >> 5;
    const int lane = tid & 31;
    const int warpM = (wid >> 1) * 32;
    const int warpN = (wid & 1) * 32;
    const uint32_t smemBase = smem_u32(dynraw);

    const int rL = (lane & 7) + 8 * ((lane >> 3) & 1);
    const int cIdx = lane >> 4;
    const int xr = rL & 7;

    auto load_stage = [&](int s, int kc) {
        const uint32_t base = smemBase + s * S_STAGE;
        #pragma unroll
        for (int i = 0; i < 4; i++) {
            int idx = tid + i * 128;
            int r = idx >> 3, j = idx & 7;
            int row = nBase + r; if (row > Nc - 1) row = Nc - 1;
            cp16_s(base + r * 128 + ((j ^ (r & 7)) << 4),
                   Asrc + (size_t)row * Dc + kc * 64 + j * 8);
        }
        #pragma unroll
        for (int i = 0; i < 4; i++) {
            int idx = tid + i * 128;
            int r = idx >> 3, j = idx & 7;
            int row = mBase + r; if (row > Nc - 1) row = Nc - 1;
            cp16_s(base + S_A_SZ + r * 128 + ((j ^ (r & 7)) << 4),
                   Bsrc + (size_t)row * Dc + kc * 64 + j * 8);
        }
    };

    float acc[2][4][4];
    #pragma unroll
    for (int mt = 0; mt < 2; mt++)
        #pragma unroll
        for (int nt = 0; nt < 4; nt++)
            #pragma unroll
            for (int q = 0; q < 4; q++) acc[mt][nt][q] = 0.0f;

    load_stage(0, 0); cp_commit();
    load_stage(1, 1); cp_commit();

    for (int kc = 0; kc < SKC; kc++) {
        const int s = kc % 3;
        cp_wait<1>();
        __syncthreads();
        if (kc + 2 < SKC) load_stage((kc + 2) % 3, kc + 2);
        cp_commit();

        const uint32_t aBase = smemBase + s * S_STAGE;
        const uint32_t bBase = aBase + S_A_SZ;
        #pragma unroll
        for (int ks = 0; ks < 4; ks++) {
            const int ch = ((2 * ks + cIdx) ^ xr) << 4;
            uint32_t aF[2][4], bF[2][4];
            #pragma unroll
            for (int mt = 0; mt < 2; mt++)
                LDSM4(aF[mt], aBase + (warpM + mt * 16 + rL) * 128 + ch);
            #pragma unroll
            for (int p = 0; p < 2; p++)
                LDSM4(bF[p], bBase + (warpN + p * 16 + rL) * 128 + ch);
            #pragma unroll
            for (int mt = 0; mt < 2; mt++)
                #pragma unroll
                for (int nt = 0; nt < 4; nt++) {
                    const int p = nt >> 1, sel = nt & 1;
                    MMA_F16(acc[mt][nt], aF[mt], bF[p][sel], bF[p][sel + 2]);
                }
        }
    }

    float* part = g_spart[sl];
    const int lr = lane >> 2;
    const int lc = (lane & 3) * 2;
    #pragma unroll
    for (int mt = 0; mt < 2; mt++) {
        const int n0 = nBase + warpM + mt * 16 + lr;
        #pragma unroll
        for (int nt = 0; nt < 4; nt++) {
            const int col = mBase + warpN + nt * 8 + lc;
            if (col < Nc) {
                if (n0 < Nc) {
                    float2 v = make_float2(acc[mt][nt][0], acc[mt][nt][1]);
                    *reinterpret_cast<float2*>(&part[((size_t)(b * Nc + n0)) * 256 + col]) = v;
                }
                if (n0 + 8 < Nc) {
                    float2 v = make_float2(acc[mt][nt][2], acc[mt][nt][3]);
                    *reinterpret_cast<float2*>(&part[((size_t)(b * Nc + n0 + 8)) * 256 + col]) = v;
                }
            }
        }
    }
}

// ---- softmax: sum 4 partials, scale, softmax, emit half attn --------------
__global__ __launch_bounds__(256) void softmax_kernel() {
    const int row = blockIdx.x;
    const int t = threadIdx.x;
    const float SC = 0.022097086912079608f;  // 1/sqrt(2048)
    __shared__ float red[256];
    float v = -1e30f;
    if (t < Nc) {
        float s = g_spart[0][(size_t)row * 256 + t] + g_spart[1][(size_t)row * 256 + t]
                + g_spart[2][(size_t)row * 256 + t] + g_spart[3][(size_t)row * 256 + t];
        v = s * SC;
    }
    red[t] = v;
    __syncthreads();
    #pragma unroll
    for (int s = 128; s > 0; s >>= 1) {
        if (t < s) red[t] = fmaxf(red[t], red[t + s]);
        __syncthreads();
    }
    float mx = red[0];
    __syncthreads();
    float e = (t < Nc) ? expf(v - mx) : 0.0f;
    red[t] = e;
    __syncthreads();
    #pragma unroll
    for (int s = 128; s > 0; s >>= 1) {
        if (t < s) red[t] += red[t + s];
        __syncthreads();
    }
    float inv = 1.0f / red[0];
    if (t < Nc) g_scoresh[(size_t)row * Nc + t] = __float2half(e * inv);
}

// ---- out = attn @ lv, f16 wmma m16n16k16 ----------------------------------
__global__ __launch_bounds__(128) void out_kernel(float* __restrict__ out) {
    const int b = blockIdx.z;
    const int nBase = blockIdx.y * 64;
    const int hBase = blockIdx.x * 64;
    const int tid = threadIdx.x;
    const int wid = tid >> 5;
    const int warpM = (wid >> 1) * 32;
    const int warpN = (wid & 1) * 32;
    __shared__ union {
        struct { __half As[64][24]; __half Bs[16][72]; } ld;
        float out[64][64];
    } sm;
    wmma::fragment<wmma::accumulator, 16, 16, 16, float> cfr[2][2];
    #pragma unroll
    for (int i = 0; i < 2; i++)
        #pragma unroll
        for (int j = 0; j < 2; j++) wmma::fill_fragment(cfr[i][j], 0.0f);
    const __half* attn = g_scoresh + (size_t)b * Nc * Nc;
    const __half* lvb  = g_lvh + (size_t)b * Nc * Hc;
    const int kTiles = (Nc + 15) / 16;  // 13
    for (int kt = 0; kt < kTiles; kt++) {
        {   // A tile: 64 rows x 16 halves = 128 uint4
            int r = tid >> 1, c8 = (tid & 1) * 8;
            int n = nBase + r, k = kt * 16 + c8;
            uint4 v = make_uint4(0, 0, 0, 0);
            if (n < Nc && k < Nc) v = *reinterpret_cast<const uint4*>(&attn[(size_t)n * Nc + k]);
            *reinterpret_cast<uint4*>(&sm.ld.As[r][c8]) = v;
        }
        {   // B tile: 16 rows x 64 halves = 128 uint4
            int r = tid >> 3, c8 = (tid & 7) * 8;
            int k = kt * 16 + r;
            uint4 v = make_uint4(0, 0, 0, 0);
            if (k < Nc) v = *reinterpret_cast<const uint4*>(&lvb[(size_t)k * Hc + hBase + c8]);
            *reinterpret_cast<uint4*>(&sm.ld.Bs[r][c8]) = v;
        }
        __syncthreads();
        {
            wmma::fragment<wmma::matrix_a, 16, 16, 16, __half, wmma::row_major> af[2];
            wmma::fragment<wmma::matrix_b, 16, 16, 16, __half, wmma::row_major> bf[2];
            #pragma unroll
            for (int i = 0; i < 2; i++)
                wmma::load_matrix_sync(af[i], &sm.ld.As[warpM + i * 16][0], 24);
            #pragma unroll
            for (int j = 0; j < 2; j++)
                wmma::load_matrix_sync(bf[j], &sm.ld.Bs[0][warpN + j * 16], 72);
            #pragma unroll
            for (int i = 0; i < 2; i++)
                #pragma unroll
                for (int j = 0; j < 2; j++) wmma::mma_sync(cfr[i][j], af[i], bf[j], cfr[i][j]);
        }
        __syncthreads();
    }
    #pragma unroll
    for (int i = 0; i < 2; i++)
        #pragma unroll
        for (int j = 0; j < 2; j++)
            wmma::store_matrix_sync(&sm.out[warpM + i * 16][warpN + j * 16], cfr[i][j], 64, wmma::mem_row_major);
    __syncthreads();
    #pragma unroll
    for (int it = 0; it < 8; it++) {
        int fid = tid + it * 128;
        int r = fid >> 4, c4 = (fid & 15) * 4;
        int n = nBase + r;
        if (n < Nc)
            *reinterpret_cast<float4*>(&out[((size_t)b * Nc + n) * Hc + hBase + c4]) =
                *reinterpret_cast<float4*>(&sm.out[r][c4]);
    }
}

// ---------------------------------------------------------------------------
extern "C" void kernel_launch(void* const* d_in, const int* in_sizes, int n_in,
                              void* d_out, int out_size) {
    (void)in_sizes; (void)n_in; (void)out_size;
    XPtrs xp;
    xp.x[0] = (const float*)d_in[0];
    xp.x[1] = (const float*)d_in[1];
    xp.x[2] = (const float*)d_in[2];
    xp.x[3] = (const float*)d_in[3];
    WPtrs wp;
    wp.w[0] = (const float*)d_in[4];
    wp.w[1] = (const float*)d_in[6];
    wp.w[2] = (const float*)d_in[8];
    wp.w[3] = (const float*)d_in[10];
    wp.w[4] = (const float*)d_in[12];
    ProjArgs pa;
    pa.bias[0] = (const float*)d_in[5];
    pa.bias[1] = (const float*)d_in[7];
    pa.bias[2] = (const float*)d_in[9];
    pa.bias[3] = (const float*)d_in[11];
    pa.bias[4] = (const float*)d_in[13];
    const float* param = (const float*)d_in[14];

    cudaFuncSetAttribute(proj_mma, cudaFuncAttributeMaxDynamicSharedMemorySize, P_DYN);
    cudaFuncSetAttribute(scores_mma, cudaFuncAttributeMaxDynamicSharedMemorySize, S_DYN);

    round_x_kernel<<<dim3(MTOK * Dc / 4 / 256, 1, 4), 256>>>(xp);
    transW_kernel<<<dim3(Hc / 32, Dc / 32, 5), dim3(32, 8)>>>(wp);
    proj_mma<<<dim3(Hc / 128, XR_ROWS / 256, 5), 256, P_DYN>>>(pa);
    add_round_kernel<<<MTOK * Dc / 4 / 256, 256>>>(param);
    scores_mma<<<dim3(4, 4, Bc * 4), 128, S_DYN>>>();
    softmax_kernel<<<MTOK, 256>>>();
    out_kernel<<<dim3(Hc / 64, (Nc + 63) / 64, Bc), 128>>>((float*)d_out);
}